// round 2
// baseline (speedup 1.0000x reference)
#include <cuda_runtime.h>
#include <math.h>

#define B    2
#define CIN  320
#define CENC 326
#define DK   64
#define DV   64
#define L    4096

#define KC     8
#define CENC_P 328   // padded to multiple of KC
#define CIN_P  320

// ---------------- scratch (device globals; no allocation allowed) ----------------
__device__ float g_Qn[B * L * DK];   // [b][l][d]  L2-normalized Q
__device__ float g_Kn[B * L * DK];   // [b][l][d]  L2-normalized K
__device__ float g_V [B * L * DV];   // [b][l][v]
__device__ float g_Wtq[CENC_P * 64]; // W transposed + zero-padded: [c][d]
__device__ float g_Wtk[CENC_P * 64];
__device__ float g_Wtv[CIN_P  * 64];

// ---------------- weight transpose: W[d][c] -> Wt[c][d], zero padding rows ------
__global__ void transpose_w_kernel(const float* __restrict__ W, int Cdim, int Cpad, int which) {
    float* Wt = (which == 0) ? g_Wtq : (which == 1) ? g_Wtk : g_Wtv;
    int idx = blockIdx.x * blockDim.x + threadIdx.x;
    if (idx < Cpad * 64) {
        int c = idx >> 6;
        int d = idx & 63;
        Wt[idx] = (c < Cdim) ? W[d * Cdim + c] : 0.f;
    }
}

// ---------------- unified projection GEMM: out[64, L] = W[64,C] @ src[C, L] ------
// z=0: Q (x_enc, +bq, L2norm)  z=1: K (x_enc, +bk, L2norm)  z=2: V (x, +bv)
// grid: (L/64, B, 3), block 256. Each thread: 4 outputs x 4 positions.
__global__ __launch_bounds__(256) void proj_kernel(const float* __restrict__ x,
                                                   const float* __restrict__ x_enc,
                                                   const float* __restrict__ bq,
                                                   const float* __restrict__ bk,
                                                   const float* __restrict__ bv) {
    int z = blockIdx.z;
    const float* src  = (z == 2) ? x : x_enc;
    const float* Wt   = (z == 0) ? g_Wtq : (z == 1) ? g_Wtk : g_Wtv;
    const float* bias = (z == 0) ? bq   : (z == 1) ? bk   : bv;
    float* dst        = (z == 0) ? g_Qn : (z == 1) ? g_Kn : g_V;
    int Cdim = (z == 2) ? CIN : CENC;
    int Cpad = (z == 2) ? CIN_P : CENC_P;

    int b  = blockIdx.y;
    int l0 = blockIdx.x * 64;

    __shared__ float Xs[KC][64];
    __shared__ float Ws[KC][64];
    __shared__ float red[16][64];
    __shared__ float nrm[64];

    int t  = threadIdx.x;
    int tx = t & 15;          // position group: pos = tx*4 + pp
    int ty = t >> 4;          // output group:   d   = ty*4 + dd

    float acc[4][4];          // [dd][pp]
#pragma unroll
    for (int i = 0; i < 4; ++i)
#pragma unroll
        for (int j = 0; j < 4; ++j) acc[i][j] = 0.f;

    const float* srcb = src + (size_t)b * Cdim * L + l0;

    int nCh = Cpad / KC;
    for (int cc = 0; cc < nCh; ++cc) {
        int c0 = cc * KC;
        __syncthreads();
#pragma unroll
        for (int r = 0; r < 2; ++r) {
            int i2  = t + r * 256;
            int row = i2 >> 6, col = i2 & 63;
            int c   = c0 + row;
            Xs[row][col] = (c < Cdim) ? srcb[(size_t)c * L + col] : 0.f;
            Ws[row][col] = Wt[c * 64 + col];          // padded rows are zero
        }
        __syncthreads();
#pragma unroll
        for (int kc = 0; kc < KC; ++kc) {
            float4 w  = *(const float4*)&Ws[kc][ty * 4];
            float4 xv = *(const float4*)&Xs[kc][tx * 4];
            acc[0][0] += w.x * xv.x; acc[0][1] += w.x * xv.y; acc[0][2] += w.x * xv.z; acc[0][3] += w.x * xv.w;
            acc[1][0] += w.y * xv.x; acc[1][1] += w.y * xv.y; acc[1][2] += w.y * xv.z; acc[1][3] += w.y * xv.w;
            acc[2][0] += w.z * xv.x; acc[2][1] += w.z * xv.y; acc[2][2] += w.z * xv.z; acc[2][3] += w.z * xv.w;
            acc[3][0] += w.w * xv.x; acc[3][1] += w.w * xv.y; acc[3][2] += w.w * xv.z; acc[3][3] += w.w * xv.w;
        }
    }

    // bias
    float bv4[4];
#pragma unroll
    for (int dd = 0; dd < 4; ++dd) {
        bv4[dd] = __ldg(bias + ty * 4 + dd);
#pragma unroll
        for (int pp = 0; pp < 4; ++pp) acc[dd][pp] += bv4[dd];
    }

    float scale[4] = {1.f, 1.f, 1.f, 1.f};
    if (z < 2) {
        // partial sum-of-squares per position
#pragma unroll
        for (int pp = 0; pp < 4; ++pp) {
            float s = acc[0][pp]*acc[0][pp] + acc[1][pp]*acc[1][pp]
                    + acc[2][pp]*acc[2][pp] + acc[3][pp]*acc[3][pp];
            red[ty][tx * 4 + pp] = s;
        }
        __syncthreads();
        if (t < 64) {
            float s = 0.f;
#pragma unroll
            for (int g = 0; g < 16; ++g) s += red[g][t];
            nrm[t] = 1.f / fmaxf(sqrtf(s), 1e-6f);
        }
        __syncthreads();
#pragma unroll
        for (int pp = 0; pp < 4; ++pp) scale[pp] = nrm[tx * 4 + pp];
    }

    // store: dst[((b*L + l)*64) + d]
#pragma unroll
    for (int pp = 0; pp < 4; ++pp) {
        int l = l0 + tx * 4 + pp;
        float4 o = make_float4(acc[0][pp] * scale[pp], acc[1][pp] * scale[pp],
                               acc[2][pp] * scale[pp], acc[3][pp] * scale[pp]);
        *(float4*)&dst[((size_t)b * L + l) * 64 + ty * 4] = o;
    }
}

// ---------------- fused cosine attention (no rescale needed: scores in [-1,1]) ----
// grid: (L/TI, B), block 256. TI=32 queries, TJ=64 key tile.
#define TI 32
#define TJ 64
#define QPAD 68   // row stride for Q tile: conflict-free quarter-warp LDS.128

__global__ __launch_bounds__(256) void attn_kernel(float* __restrict__ out) {
    extern __shared__ float sm[];
    float* Qs = sm;                       // [TI][QPAD]
    float* Ks = Qs + TI * QPAD;           // [TJ][QPAD]
    float* Vs = Ks + TJ * QPAD;           // [TJ][64]
    float* Ps = Vs + TJ * 64;             // [TJ][TI]  (j-major for conflict-free i reads)

    int t   = threadIdx.x;
    int il  = t & 31;          // query row within tile
    int grp = t >> 5;          // 0..7 : j-group (phase1) / v-group (phase2)
    int b   = blockIdx.y;
    int i0  = blockIdx.x * TI;

    // load Q tile (TI x 64) -> padded shared
    for (int idx = t; idx < TI * 16; idx += 256) {
        int r = idx >> 4, c4 = idx & 15;
        float4 q = ((const float4*)(g_Qn + ((size_t)b * L + i0 + r) * DK))[c4];
        *(float4*)&Qs[r * QPAD + c4 * 4] = q;
    }

    float acc[8];
#pragma unroll
    for (int k = 0; k < 8; ++k) acc[k] = 0.f;
    float dsum = 0.f;

    for (int j0 = 0; j0 < L; j0 += TJ) {
        __syncthreads();   // protect prior-tile Ps/Ks/Vs consumers
        // load K, V tiles (each TJ x 64 floats)
        for (int idx = t; idx < TJ * 16; idx += 256) {
            int r = idx >> 4, c4 = idx & 15;
            float4 kv = ((const float4*)(g_Kn + ((size_t)b * L + j0 + r) * DK))[c4];
            *(float4*)&Ks[r * QPAD + c4 * 4] = kv;
            float4 vv = ((const float4*)(g_V + ((size_t)b * L + j0 + r) * DV))[c4];
            *(float4*)&Vs[r * 64 + c4 * 4] = vv;
        }
        __syncthreads();

        // phase 1: 8 scores per thread: S[il][grp*8+jj] = dot64(Q[il], K[j])
        float s[8];
#pragma unroll
        for (int jj = 0; jj < 8; ++jj) s[jj] = 0.f;
#pragma unroll
        for (int c = 0; c < 64; c += 4) {
            float4 q = *(const float4*)&Qs[il * QPAD + c];
#pragma unroll
            for (int jj = 0; jj < 8; ++jj) {
                float4 kk = *(const float4*)&Ks[(grp * 8 + jj) * QPAD + c];
                s[jj] += q.x * kk.x + q.y * kk.y + q.z * kk.z + q.w * kk.w;
            }
        }
#pragma unroll
        for (int jj = 0; jj < 8; ++jj)
            Ps[(grp * 8 + jj) * TI + il] = __expf(s[jj]);
        __syncthreads();

        // phase 2: acc[v] += P[j][il] * V[j][grp*8+v];  denom += P
#pragma unroll 4
        for (int j = 0; j < TJ; ++j) {
            float p = Ps[j * TI + il];
            dsum += p;
            float4 v0 = *(const float4*)&Vs[j * 64 + grp * 8];
            float4 v1 = *(const float4*)&Vs[j * 64 + grp * 8 + 4];
            acc[0] += p * v0.x; acc[1] += p * v0.y;
            acc[2] += p * v0.z; acc[3] += p * v0.w;
            acc[4] += p * v1.x; acc[5] += p * v1.y;
            acc[6] += p * v1.z; acc[7] += p * v1.w;
        }
    }

    // write: out[b][v][i] = acc[v] / denom
    float inv = 1.f / dsum;           // dsum >= L*e^-1 > 0, always finite
    int i = i0 + il;
#pragma unroll
    for (int k = 0; k < 8; ++k)
        out[((size_t)b * DV + grp * 8 + k) * L + i] = acc[k] * inv;
}

// ---------------- launch ----------------
extern "C" void kernel_launch(void* const* d_in, const int* in_sizes, int n_in,
                              void* d_out, int out_size) {
    const float* x     = (const float*)d_in[0];
    const float* x_enc = (const float*)d_in[1];
    const float* Wq    = (const float*)d_in[2];
    const float* bq    = (const float*)d_in[3];
    const float* Wk    = (const float*)d_in[4];
    const float* bk    = (const float*)d_in[5];
    const float* Wv    = (const float*)d_in[6];
    const float* bv    = (const float*)d_in[7];
    float* out = (float*)d_out;

    // weight transposes (+ zero padding)
    transpose_w_kernel<<<(CENC_P * 64 + 255) / 256, 256>>>(Wq, CENC, CENC_P, 0);
    transpose_w_kernel<<<(CENC_P * 64 + 255) / 256, 256>>>(Wk, CENC, CENC_P, 1);
    transpose_w_kernel<<<(CIN_P  * 64 + 255) / 256, 256>>>(Wv, CIN,  CIN_P,  2);

    // unified projection GEMM (Q, K, V in one grid)
    proj_kernel<<<dim3(L / 64, B, 3), 256>>>(x, x_enc, bq, bk, bv);

    // fused attention
    int smem = (TI * QPAD + TJ * QPAD + TJ * 64 + TJ * TI) * (int)sizeof(float);
    static bool attr_set = false;
    if (!attr_set) {
        cudaFuncSetAttribute(attn_kernel, cudaFuncAttributeMaxDynamicSharedMemorySize, smem);
        attr_set = true;
    }
    attn_kernel<<<dim3(L / TI, B), 256, smem>>>(out);
}

// round 4
// speedup vs baseline: 3.2926x; 3.2926x over previous
#include <cuda_runtime.h>
#include <cuda_bf16.h>
#include <math.h>
#include <stdint.h>

#define B    2
#define CIN  320
#define CENC 326
#define L    4096

#define KC     8
#define CENC_P 328
#define CIN_P  320

#define STRD 72      // bf16 row stride in smem tiles (conflict-free ldmatrix)

// ---------------- scratch (device globals) ----------------
__device__ __nv_bfloat16 g_Qhi[B * L * 64], g_Qlo[B * L * 64];
__device__ __nv_bfloat16 g_Khi[B * L * 64], g_Klo[B * L * 64];
__device__ __nv_bfloat16 g_Vthi[B * 64 * L], g_Vtlo[B * 64 * L];   // [b][v][l]
__device__ float g_Wtq[CENC_P * 64];
__device__ float g_Wtk[CENC_P * 64];
__device__ float g_Wtv[CIN_P  * 64];

// ---------------- helpers ----------------
__device__ __forceinline__ uint32_t smem_u32(const void* p) {
    uint32_t a;
    asm("{ .reg .u64 t; cvta.to.shared.u64 t, %1; cvt.u32.u64 %0, t; }" : "=r"(a) : "l"(p));
    return a;
}
__device__ __forceinline__ void ldsm4(uint32_t r[4], uint32_t addr) {
    asm volatile("ldmatrix.sync.aligned.m8n8.x4.shared.b16 {%0,%1,%2,%3}, [%4];"
        : "=r"(r[0]), "=r"(r[1]), "=r"(r[2]), "=r"(r[3]) : "r"(addr));
}
__device__ __forceinline__ void mma_bf16(float c[4], const uint32_t a[4],
                                         uint32_t b0, uint32_t b1) {
    asm volatile("mma.sync.aligned.m16n8k16.row.col.f32.bf16.bf16.f32 "
        "{%0,%1,%2,%3}, {%4,%5,%6,%7}, {%8,%9}, {%0,%1,%2,%3};"
        : "+f"(c[0]), "+f"(c[1]), "+f"(c[2]), "+f"(c[3])
        : "r"(a[0]), "r"(a[1]), "r"(a[2]), "r"(a[3]), "r"(b0), "r"(b1));
}

// ---------------- weight transpose ----------------
__global__ void transpose_w_kernel(const float* __restrict__ W, int Cdim, int Cpad, int which) {
    float* Wt = (which == 0) ? g_Wtq : (which == 1) ? g_Wtk : g_Wtv;
    int idx = blockIdx.x * blockDim.x + threadIdx.x;
    if (idx < Cpad * 64) {
        int c = idx >> 6, d = idx & 63;
        Wt[idx] = (c < Cdim) ? W[d * Cdim + c] : 0.f;
    }
}

// ---------------- projections (fp32 GEMM, bf16 hi/lo epilogue) ----------------
__global__ __launch_bounds__(256) void proj_kernel(const float* __restrict__ x,
                                                   const float* __restrict__ x_enc,
                                                   const float* __restrict__ bq,
                                                   const float* __restrict__ bk,
                                                   const float* __restrict__ bv) {
    int z = blockIdx.z;
    const float* src  = (z == 2) ? x : x_enc;
    const float* Wt   = (z == 0) ? g_Wtq : (z == 1) ? g_Wtk : g_Wtv;
    const float* bias = (z == 0) ? bq : (z == 1) ? bk : bv;
    int Cdim = (z == 2) ? CIN : CENC;
    int Cpad = (z == 2) ? CIN_P : CENC_P;

    int b  = blockIdx.y;
    int l0 = blockIdx.x * 64;

    __shared__ float Xs[KC][64];
    __shared__ float Ws[KC][64];
    __shared__ float red[16][64];
    __shared__ float nrm[64];

    int t  = threadIdx.x;
    int tx = t & 15;
    int ty = t >> 4;

    float acc[4][4];
#pragma unroll
    for (int i = 0; i < 4; ++i)
#pragma unroll
        for (int j = 0; j < 4; ++j) acc[i][j] = 0.f;

    const float* srcb = src + (size_t)b * Cdim * L + l0;

    int nCh = Cpad / KC;
    for (int cc = 0; cc < nCh; ++cc) {
        int c0 = cc * KC;
        __syncthreads();
#pragma unroll
        for (int r = 0; r < 2; ++r) {
            int i2 = t + r * 256;
            int row = i2 >> 6, col = i2 & 63;
            int c = c0 + row;
            Xs[row][col] = (c < Cdim) ? srcb[(size_t)c * L + col] : 0.f;
            Ws[row][col] = Wt[c * 64 + col];
        }
        __syncthreads();
#pragma unroll
        for (int kc = 0; kc < KC; ++kc) {
            float4 w  = *(const float4*)&Ws[kc][ty * 4];
            float4 xv = *(const float4*)&Xs[kc][tx * 4];
            acc[0][0] += w.x*xv.x; acc[0][1] += w.x*xv.y; acc[0][2] += w.x*xv.z; acc[0][3] += w.x*xv.w;
            acc[1][0] += w.y*xv.x; acc[1][1] += w.y*xv.y; acc[1][2] += w.y*xv.z; acc[1][3] += w.y*xv.w;
            acc[2][0] += w.z*xv.x; acc[2][1] += w.z*xv.y; acc[2][2] += w.z*xv.z; acc[2][3] += w.z*xv.w;
            acc[3][0] += w.w*xv.x; acc[3][1] += w.w*xv.y; acc[3][2] += w.w*xv.z; acc[3][3] += w.w*xv.w;
        }
    }

#pragma unroll
    for (int dd = 0; dd < 4; ++dd) {
        float bb = __ldg(bias + ty * 4 + dd);
#pragma unroll
        for (int pp = 0; pp < 4; ++pp) acc[dd][pp] += bb;
    }

    if (z < 2) {
#pragma unroll
        for (int pp = 0; pp < 4; ++pp) {
            float s = acc[0][pp]*acc[0][pp] + acc[1][pp]*acc[1][pp]
                    + acc[2][pp]*acc[2][pp] + acc[3][pp]*acc[3][pp];
            red[ty][tx * 4 + pp] = s;
        }
        __syncthreads();
        if (t < 64) {
            float s = 0.f;
#pragma unroll
            for (int g = 0; g < 16; ++g) s += red[g][t];
            nrm[t] = 1.f / fmaxf(sqrtf(s), 1e-6f);
        }
        __syncthreads();

        __nv_bfloat16* dh = (z == 0) ? g_Qhi : g_Khi;
        __nv_bfloat16* dl = (z == 0) ? g_Qlo : g_Klo;
#pragma unroll
        for (int pp = 0; pp < 4; ++pp) {
            int l = l0 + tx * 4 + pp;
            float sc = nrm[tx * 4 + pp];
            __nv_bfloat16 th[4], tl[4];
#pragma unroll
            for (int dd = 0; dd < 4; ++dd) {
                float v = acc[dd][pp] * sc;
                th[dd] = __float2bfloat16(v);
                tl[dd] = __float2bfloat16(v - __bfloat162float(th[dd]));
            }
            size_t o = ((size_t)b * L + l) * 64 + ty * 4;
            *(uint2*)&dh[o] = *(uint2*)th;
            *(uint2*)&dl[o] = *(uint2*)tl;
        }
    } else {
        // V: store transposed [b][v][l] bf16 hi/lo
#pragma unroll
        for (int dd = 0; dd < 4; ++dd) {
            int d = ty * 4 + dd;
            __nv_bfloat16 th[4], tl[4];
#pragma unroll
            for (int pp = 0; pp < 4; ++pp) {
                float v = acc[dd][pp];
                th[pp] = __float2bfloat16(v);
                tl[pp] = __float2bfloat16(v - __bfloat162float(th[pp]));
            }
            size_t o = ((size_t)b * 64 + d) * L + l0 + tx * 4;
            *(uint2*)&g_Vthi[o] = *(uint2*)th;
            *(uint2*)&g_Vtlo[o] = *(uint2*)tl;
        }
    }
}

// ---------------- mma.sync flash attention ----------------
// grid (L/64, B), 128 threads (4 warps), warp w owns query rows w*16..w*16+15.
// smem: 4 bf16 tiles [64][STRD]: KH, KL, VH, VL (V transposed: rows=v, cols=j).
__global__ __launch_bounds__(128) void attn_kernel(float* __restrict__ out) {
    extern __shared__ char sm[];
    const uint32_t sb = smem_u32(sm);
    const int t = threadIdx.x, lane = t & 31, w = t >> 5;
    const int b = blockIdx.y, i0 = blockIdx.x * 64;
    const int gid = lane >> 2, tig = lane & 3;
    const int lr = lane & 7, lg = lane >> 3;

    const uint32_t KH = 0, KL = 9216, VH = 18432, VL = 27648;

    // ldmatrix per-lane address offsets (bytes) within a [64][STRD] bf16 tile
    const uint32_t offA = (uint32_t)(((lr + ((lg & 1) << 3)) * STRD + ((lg >> 1) << 3)) * 2);
    const uint32_t offB = (uint32_t)(((lr + ((lg >> 1) << 3)) * STRD + ((lg & 1) << 3)) * 2);

    // ---- stage Q (hi/lo) into KH/KL, build persistent A fragments
    {
        const uint4* qh = (const uint4*)(g_Qhi + ((size_t)b * L + i0) * 64);
        const uint4* ql = (const uint4*)(g_Qlo + ((size_t)b * L + i0) * 64);
        for (int idx = t; idx < 512; idx += 128) {
            int r = idx >> 3, c = idx & 7;
            uint32_t so = (uint32_t)((r * STRD + c * 8) * 2);
            *(uint4*)(sm + KH + so) = qh[idx];
            *(uint4*)(sm + KL + so) = ql[idx];
        }
    }
    __syncthreads();
    uint32_t qfh[4][4], qfl[4][4];
    {
        uint32_t base = sb + (uint32_t)(w * 16 * STRD * 2) + offA;
#pragma unroll
        for (int kb = 0; kb < 4; ++kb) {
            ldsm4(qfh[kb], base + KH + kb * 32);
            ldsm4(qfl[kb], base + KL + kb * 32);
        }
    }

    float O[8][4];
#pragma unroll
    for (int n = 0; n < 8; ++n)
#pragma unroll
        for (int q = 0; q < 4; ++q) O[n][q] = 0.f;
    float dl = 0.f, dh = 0.f;

    const uint32_t bB = sb + offB;

    for (int tile = 0; tile < 64; ++tile) {
        int j0 = tile * 64;
        __syncthreads();
        // load K (hi/lo, rows=j, cols=d) and Vt (hi/lo, rows=v, cols=j)
        for (int idx = t; idx < 512; idx += 128) {
            int r = idx >> 3, c = idx & 7;
            uint32_t so = (uint32_t)((r * STRD + c * 8) * 2);
            size_t kg = ((size_t)b * L + j0 + r) * 64 + c * 8;
            *(uint4*)(sm + KH + so) = *(const uint4*)(g_Khi + kg);
            *(uint4*)(sm + KL + so) = *(const uint4*)(g_Klo + kg);
            size_t vg = ((size_t)b * 64 + r) * L + j0 + c * 8;
            *(uint4*)(sm + VH + so) = *(const uint4*)(g_Vthi + vg);
            *(uint4*)(sm + VL + so) = *(const uint4*)(g_Vtlo + vg);
        }
        __syncthreads();

        // ---- S = Qhi Khi^T + Qhi Klo^T + Qlo Khi^T  (fp32 accum)
        float S[8][4];
#pragma unroll
        for (int n = 0; n < 8; ++n)
#pragma unroll
            for (int q = 0; q < 4; ++q) S[n][q] = 0.f;

#pragma unroll
        for (int pass = 0; pass < 3; ++pass) {
            const uint32_t Koff = (pass == 1) ? KL : KH;
            const uint32_t (*A)[4] = (pass == 2) ? qfl : qfh;
#pragma unroll
            for (int kb = 0; kb < 4; ++kb) {
#pragma unroll
                for (int np = 0; np < 4; ++np) {
                    uint32_t bf[4];
                    ldsm4(bf, bB + Koff + (uint32_t)(np * 16 * STRD * 2) + kb * 32);
                    mma_bf16(S[np * 2],     A[kb], bf[0], bf[1]);
                    mma_bf16(S[np * 2 + 1], A[kb], bf[2], bf[3]);
                }
            }
        }

        // ---- exp (no max shift needed: |S|<=1+eps), row sums, hi/lo pack -> P frags
        float rl = 0.f, rh = 0.f;
#pragma unroll
        for (int n = 0; n < 8; ++n) {
#pragma unroll
            for (int q = 0; q < 4; ++q) S[n][q] = __expf(S[n][q]);
            rl += S[n][0] + S[n][1];
            rh += S[n][2] + S[n][3];
        }
        dl += rl; dh += rh;

        uint32_t phi[4][4], plo[4][4];
#pragma unroll
        for (int jb = 0; jb < 4; ++jb) {
#pragma unroll
            for (int rp = 0; rp < 4; ++rp) {
                int n = jb * 2 + (rp >> 1);
                float e0 = S[n][(rp & 1) * 2 + 0];
                float e1 = S[n][(rp & 1) * 2 + 1];
                uint32_t hh;
                asm("cvt.rn.bf16x2.f32 %0, %1, %2;" : "=r"(hh) : "f"(e1), "f"(e0));
                phi[jb][rp] = hh;
                float l0 = e0 - __uint_as_float(hh << 16);
                float l1 = e1 - __uint_as_float(hh & 0xffff0000u);
                uint32_t ll;
                asm("cvt.rn.bf16x2.f32 %0, %1, %2;" : "=r"(ll) : "f"(l1), "f"(l0));
                plo[jb][rp] = ll;
            }
        }

        // ---- O += Phi Vhi + Phi Vlo + Plo Vhi
#pragma unroll
        for (int pass = 0; pass < 3; ++pass) {
            const uint32_t Voff = (pass == 1) ? VL : VH;
            const uint32_t (*A)[4] = (pass == 2) ? plo : phi;
#pragma unroll
            for (int jb = 0; jb < 4; ++jb) {
#pragma unroll
                for (int vp = 0; vp < 4; ++vp) {
                    uint32_t bf[4];
                    ldsm4(bf, bB + Voff + (uint32_t)(vp * 16 * STRD * 2) + jb * 32);
                    mma_bf16(O[vp * 2],     A[jb], bf[0], bf[1]);
                    mma_bf16(O[vp * 2 + 1], A[jb], bf[2], bf[3]);
                }
            }
        }
    }

    // row-sum reduce across the 4 lanes of each row group
    dl += __shfl_xor_sync(0xffffffffu, dl, 1);
    dl += __shfl_xor_sync(0xffffffffu, dl, 2);
    dh += __shfl_xor_sync(0xffffffffu, dh, 1);
    dh += __shfl_xor_sync(0xffffffffu, dh, 2);
    float invl = 1.f / dl, invh = 1.f / dh;

    // ---- write out[b][v][i] via smem transpose (reuse tile smem as float [64][68])
    __syncthreads();
    float* Os = (float*)sm;
    {
        int ir = w * 16 + gid;
#pragma unroll
        for (int n = 0; n < 8; ++n) {
            int v0 = n * 8 + tig * 2;
            Os[v0 * 68 + ir]           = O[n][0] * invl;
            Os[(v0 + 1) * 68 + ir]     = O[n][1] * invl;
            Os[v0 * 68 + ir + 8]       = O[n][2] * invh;
            Os[(v0 + 1) * 68 + ir + 8] = O[n][3] * invh;
        }
    }
    __syncthreads();
    {
        int v = t >> 1, hc = (t & 1) * 32;
        float* dst = out + ((size_t)b * 64 + v) * L + i0 + hc;
        const float* srcp = Os + v * 68 + hc;
#pragma unroll
        for (int c = 0; c < 8; ++c)
            *(float4*)(dst + c * 4) = *(const float4*)(srcp + c * 4);
    }
}

// ---------------- launch ----------------
extern "C" void kernel_launch(void* const* d_in, const int* in_sizes, int n_in,
                              void* d_out, int out_size) {
    const float* x     = (const float*)d_in[0];
    const float* x_enc = (const float*)d_in[1];
    const float* Wq    = (const float*)d_in[2];
    const float* bq    = (const float*)d_in[3];
    const float* Wk    = (const float*)d_in[4];
    const float* bk    = (const float*)d_in[5];
    const float* Wv    = (const float*)d_in[6];
    const float* bv    = (const float*)d_in[7];
    float* out = (float*)d_out;

    transpose_w_kernel<<<(CENC_P * 64 + 255) / 256, 256>>>(Wq, CENC, CENC_P, 0);
    transpose_w_kernel<<<(CENC_P * 64 + 255) / 256, 256>>>(Wk, CENC, CENC_P, 1);
    transpose_w_kernel<<<(CIN_P  * 64 + 255) / 256, 256>>>(Wv, CIN,  CIN_P,  2);

    proj_kernel<<<dim3(L / 64, B, 3), 256>>>(x, x_enc, bq, bk, bv);

    attn_kernel<<<dim3(L / 64, B), 128, 36864>>>(out);
}

// round 6
// speedup vs baseline: 4.1982x; 1.2750x over previous
#include <cuda_runtime.h>
#include <cuda_bf16.h>
#include <math.h>
#include <stdint.h>

#define B    2
#define CIN  320
#define CENC 326
#define L    4096

#define CENC_P 336   // padded to multiple of 16
#define CIN_P  320

#define STRD 72      // bf16 row stride in attention smem tiles (144B, 16B-aligned)
#define WST  24      // bf16 row stride in proj smem tiles (48B rows: 16B-aligned, conflict-free)

// ---------------- scratch (device globals) ----------------
__device__ __nv_bfloat16 g_Qhi[B * L * 64], g_Qlo[B * L * 64];
__device__ __nv_bfloat16 g_Khi[B * L * 64], g_Klo[B * L * 64];
__device__ __nv_bfloat16 g_Vthi[B * 64 * L], g_Vtlo[B * 64 * L];   // [b][v][l]
__device__ __nv_bfloat16 g_Whq[64 * CENC_P], g_Wlq[64 * CENC_P];   // [d][c] hi/lo
__device__ __nv_bfloat16 g_Whk[64 * CENC_P], g_Wlk[64 * CENC_P];
__device__ __nv_bfloat16 g_Whv[64 * CIN_P],  g_Wlv[64 * CIN_P];

// ---------------- helpers ----------------
__device__ __forceinline__ uint32_t smem_u32(const void* p) {
    uint32_t a;
    asm("{ .reg .u64 t; cvta.to.shared.u64 t, %1; cvt.u32.u64 %0, t; }" : "=r"(a) : "l"(p));
    return a;
}
__device__ __forceinline__ void ldsm4(uint32_t r[4], uint32_t addr) {
    asm volatile("ldmatrix.sync.aligned.m8n8.x4.shared.b16 {%0,%1,%2,%3}, [%4];"
        : "=r"(r[0]), "=r"(r[1]), "=r"(r[2]), "=r"(r[3]) : "r"(addr));
}
__device__ __forceinline__ void mma_bf16(float c[4], const uint32_t a[4],
                                         uint32_t b0, uint32_t b1) {
    asm volatile("mma.sync.aligned.m16n8k16.row.col.f32.bf16.bf16.f32 "
        "{%0,%1,%2,%3}, {%4,%5,%6,%7}, {%8,%9}, {%0,%1,%2,%3};"
        : "+f"(c[0]), "+f"(c[1]), "+f"(c[2]), "+f"(c[3])
        : "r"(a[0]), "r"(a[1]), "r"(a[2]), "r"(a[3]), "r"(b0), "r"(b1));
}
__device__ __forceinline__ void cpa16(uint32_t dst, const void* src) {
    asm volatile("cp.async.cg.shared.global [%0], [%1], 16;" :: "r"(dst), "l"(src));
}
#define CPA_COMMIT() asm volatile("cp.async.commit_group;" ::: "memory")
#define CPA_WAIT1()  asm volatile("cp.async.wait_group 1;" ::: "memory")
#define CPA_WAIT0()  asm volatile("cp.async.wait_group 0;" ::: "memory")

// ---------------- weight prep: W[d][c] fp32 -> bf16 hi/lo [d][Cpad] ----------------
__global__ void prep_w_kernel(const float* __restrict__ W, int Cdim, int Cpad, int which) {
    __nv_bfloat16* Wh = (which == 0) ? g_Whq : (which == 1) ? g_Whk : g_Whv;
    __nv_bfloat16* Wl = (which == 0) ? g_Wlq : (which == 1) ? g_Wlk : g_Wlv;
    int idx = blockIdx.x * blockDim.x + threadIdx.x;
    if (idx < 64 * Cpad) {
        int d = idx / Cpad, c = idx - d * Cpad;
        float v = (c < Cdim) ? W[d * Cdim + c] : 0.f;
        __nv_bfloat16 h = __float2bfloat16(v);
        Wh[idx] = h;
        Wl[idx] = __float2bfloat16(v - __bfloat162float(h));
    }
}

// ---------------- tensor-core projections ----------------
// grid (L/64, B, 3), 128 threads. out[64 d][64 l] = W[64][C] @ X[C][64-l-tile]
// smem: 4 bf16 tiles [64][WST] = 3072B each: Xh @0, Xl @3072, Whs @6144, Wls @9216
__global__ __launch_bounds__(128) void proj_kernel(const float* __restrict__ x,
                                                   const float* __restrict__ x_enc,
                                                   const float* __restrict__ bq,
                                                   const float* __restrict__ bk,
                                                   const float* __restrict__ bv) {
    int z = blockIdx.z, b = blockIdx.y, l0 = blockIdx.x * 64;
    const float* src  = (z == 2) ? x : x_enc;
    const __nv_bfloat16* Wh = (z == 0) ? g_Whq : (z == 1) ? g_Whk : g_Whv;
    const __nv_bfloat16* Wl = (z == 0) ? g_Wlq : (z == 1) ? g_Wlk : g_Wlv;
    const float* bias = (z == 0) ? bq : (z == 1) ? bk : bv;
    int Cdim = (z == 2) ? CIN : CENC;
    int Cpad = (z == 2) ? CIN_P : CENC_P;

    extern __shared__ char psm[];
    __nv_bfloat16* Xh  = (__nv_bfloat16*)(psm);
    __nv_bfloat16* Xl  = (__nv_bfloat16*)(psm + 3072);
    __nv_bfloat16* Whs = (__nv_bfloat16*)(psm + 6144);
    __nv_bfloat16* Wls = (__nv_bfloat16*)(psm + 9216);
    __shared__ float nrmA[64];
    uint32_t sb = smem_u32(psm);

    int t = threadIdx.x, lane = t & 31, w = t >> 5;
    int gid = lane >> 2, tig = lane & 3, lr = lane & 7, lg = lane >> 3;

    float S[8][4];
#pragma unroll
    for (int n = 0; n < 8; ++n)
#pragma unroll
        for (int q = 0; q < 4; ++q) S[n][q] = 0.f;

    const float* srcb = src + (size_t)b * Cdim * L + l0;
    const uint32_t offB = (uint32_t)(((lr + (lg >> 1) * 8) * WST + (lg & 1) * 8) * 2);
    const uint32_t bX = sb + offB;

    int nCh = Cpad / 16;
    for (int ch = 0; ch < nCh; ++ch) {
        int c0 = ch * 16;
        __syncthreads();
        // stage X tile [16 c][64 l] -> smem [l][c] bf16 hi/lo (converted)
#pragma unroll
        for (int i = 0; i < 8; ++i) {
            int idx = t + i * 128;
            int c = idx >> 6, l = idx & 63;
            float v = (c0 + c < Cdim) ? __ldg(srcb + (size_t)(c0 + c) * L + l) : 0.f;
            __nv_bfloat16 h = __float2bfloat16(v);
            Xh[l * WST + c] = h;
            Xl[l * WST + c] = __float2bfloat16(v - __bfloat162float(h));
        }
        // stage W tile [64 d][16 c] hi/lo
#pragma unroll
        for (int i = 0; i < 4; ++i) {
            int idx = t + i * 128;
            int d = idx >> 3, cp = idx & 7;
            *(uint32_t*)&Whs[d * WST + cp * 2] = *(const uint32_t*)&Wh[d * Cpad + c0 + cp * 2];
            *(uint32_t*)&Wls[d * WST + cp * 2] = *(const uint32_t*)&Wl[d * Cpad + c0 + cp * 2];
        }
        __syncthreads();

        // A fragments (W rows w*16..w*16+15, k = 16) via direct LDS.32
        uint32_t ah[4], al[4];
        {
            int r0 = (w * 16 + gid) * WST, r8 = (w * 16 + gid + 8) * WST;
            ah[0] = *(const uint32_t*)&Whs[r0 + tig * 2];
            ah[1] = *(const uint32_t*)&Whs[r8 + tig * 2];
            ah[2] = *(const uint32_t*)&Whs[r0 + tig * 2 + 8];
            ah[3] = *(const uint32_t*)&Whs[r8 + tig * 2 + 8];
            al[0] = *(const uint32_t*)&Wls[r0 + tig * 2];
            al[1] = *(const uint32_t*)&Wls[r8 + tig * 2];
            al[2] = *(const uint32_t*)&Wls[r0 + tig * 2 + 8];
            al[3] = *(const uint32_t*)&Wls[r8 + tig * 2 + 8];
        }

#pragma unroll
        for (int np = 0; np < 4; ++np) {
            uint32_t bh[4], bl[4];
            ldsm4(bh, bX + (uint32_t)(np * 16 * WST * 2));
            mma_bf16(S[np * 2],     ah, bh[0], bh[1]);
            mma_bf16(S[np * 2 + 1], ah, bh[2], bh[3]);
            mma_bf16(S[np * 2],     al, bh[0], bh[1]);
            mma_bf16(S[np * 2 + 1], al, bh[2], bh[3]);
            ldsm4(bl, bX + 3072u + (uint32_t)(np * 16 * WST * 2));
            mma_bf16(S[np * 2],     ah, bl[0], bl[1]);
            mma_bf16(S[np * 2 + 1], ah, bl[2], bl[3]);
        }
    }

    float b0v = __ldg(bias + w * 16 + gid);
    float b8v = __ldg(bias + w * 16 + gid + 8);

    float* Osm = (float*)psm;   // [64][68] floats = 17408B
    __syncthreads();

    if (z < 2) {
        // write [l][d] with bias
#pragma unroll
        for (int n = 0; n < 8; ++n) {
            int lc = n * 8 + tig * 2, d0 = w * 16 + gid;
            Osm[lc * 68 + d0]           = S[n][0] + b0v;
            Osm[(lc + 1) * 68 + d0]     = S[n][1] + b0v;
            Osm[lc * 68 + d0 + 8]       = S[n][2] + b8v;
            Osm[(lc + 1) * 68 + d0 + 8] = S[n][3] + b8v;
        }
        __syncthreads();
        if (t < 64) {
            float ss = 0.f;
#pragma unroll
            for (int d = 0; d < 64; ++d) { float v = Osm[t * 68 + d]; ss += v * v; }
            nrmA[t] = 1.f / fmaxf(sqrtf(ss), 1e-6f);
        }
        __syncthreads();
        __nv_bfloat16* dh = (z == 0) ? g_Qhi : g_Khi;
        __nv_bfloat16* dl = (z == 0) ? g_Qlo : g_Klo;
        int l = t & 63, dg = t >> 6;              // 32 d's per thread
        float sc = nrmA[l];
        size_t obase = ((size_t)b * L + l0 + l) * 64 + dg * 32;
#pragma unroll
        for (int i = 0; i < 8; ++i) {
            __nv_bfloat16 th[4], tl[4];
#pragma unroll
            for (int k = 0; k < 4; ++k) {
                float v = Osm[l * 68 + dg * 32 + i * 4 + k] * sc;
                th[k] = __float2bfloat16(v);
                tl[k] = __float2bfloat16(v - __bfloat162float(th[k]));
            }
            *(uint2*)&dh[obase + i * 4] = *(uint2*)th;
            *(uint2*)&dl[obase + i * 4] = *(uint2*)tl;
        }
    } else {
        // V: write [d][l] with bias, then store transposed [v][l]
#pragma unroll
        for (int n = 0; n < 8; ++n) {
            int lc = n * 8 + tig * 2, d0 = w * 16 + gid;
            Osm[d0 * 68 + lc]           = S[n][0] + b0v;
            Osm[d0 * 68 + lc + 1]       = S[n][1] + b0v;
            Osm[(d0 + 8) * 68 + lc]     = S[n][2] + b8v;
            Osm[(d0 + 8) * 68 + lc + 1] = S[n][3] + b8v;
        }
        __syncthreads();
        int v = t >> 1, half = t & 1;
        size_t obase = ((size_t)b * 64 + v) * L + l0 + half * 32;
#pragma unroll
        for (int i = 0; i < 8; ++i) {
            __nv_bfloat16 th[4], tl[4];
#pragma unroll
            for (int k = 0; k < 4; ++k) {
                float vv = Osm[v * 68 + half * 32 + i * 4 + k];
                th[k] = __float2bfloat16(vv);
                tl[k] = __float2bfloat16(vv - __bfloat162float(th[k]));
            }
            *(uint2*)&g_Vthi[obase + i * 4] = *(uint2*)th;
            *(uint2*)&g_Vtlo[obase + i * 4] = *(uint2*)tl;
        }
    }
}

// ---------------- mma.sync flash attention (cp.async double-buffered) ----------------
// grid (L/64, B), 128 threads (4 warps), warp w owns query rows w*16..w*16+15.
#define KH 0u
#define KL 9216u
#define VH 18432u
#define VL 27648u
#define STAGEB 36864u

__device__ __forceinline__ void load_kv(uint32_t sbase, int b, int j0, int t) {
#pragma unroll
    for (int i = 0; i < 4; ++i) {
        int idx = t + i * 128;
        int r = idx >> 3, c = idx & 7;
        uint32_t so = (uint32_t)((r * STRD + c * 8) * 2);
        size_t kg = ((size_t)b * L + j0 + r) * 64 + c * 8;
        cpa16(sbase + KH + so, g_Khi + kg);
        cpa16(sbase + KL + so, g_Klo + kg);
        size_t vg = ((size_t)b * 64 + r) * L + j0 + c * 8;
        cpa16(sbase + VH + so, g_Vthi + vg);
        cpa16(sbase + VL + so, g_Vtlo + vg);
    }
}

__global__ __launch_bounds__(128) void attn_kernel(float* __restrict__ out) {
    extern __shared__ char sm[];
    const uint32_t sb = smem_u32(sm);
    const int t = threadIdx.x, lane = t & 31, w = t >> 5;
    const int b = blockIdx.y, i0 = blockIdx.x * 64;
    const int gid = lane >> 2, tig = lane & 3;
    const int lr = lane & 7, lg = lane >> 3;

    const uint32_t offA = (uint32_t)(((lr + ((lg & 1) << 3)) * STRD + ((lg >> 1) << 3)) * 2);
    const uint32_t offB = (uint32_t)(((lr + ((lg >> 1) << 3)) * STRD + ((lg & 1) << 3)) * 2);

    // ---- stage Q (hi/lo) into stage-0 KH/KL, build persistent A fragments
    {
        const uint4* qh = (const uint4*)(g_Qhi + ((size_t)b * L + i0) * 64);
        const uint4* ql = (const uint4*)(g_Qlo + ((size_t)b * L + i0) * 64);
        for (int idx = t; idx < 512; idx += 128) {
            int r = idx >> 3, c = idx & 7;
            uint32_t so = (uint32_t)((r * STRD + c * 8) * 2);
            *(uint4*)(sm + KH + so) = qh[idx];
            *(uint4*)(sm + KL + so) = ql[idx];
        }
    }
    __syncthreads();
    uint32_t qfh[4][4], qfl[4][4];
    {
        uint32_t base = sb + (uint32_t)(w * 16 * STRD * 2) + offA;
#pragma unroll
        for (int kb = 0; kb < 4; ++kb) {
            ldsm4(qfh[kb], base + KH + kb * 32);
            ldsm4(qfl[kb], base + KL + kb * 32);
        }
    }
    __syncthreads();

    // prologue: async-load tile 0 into stage 0
    load_kv(sb, b, 0, t);
    CPA_COMMIT();

    float O[8][4];
#pragma unroll
    for (int n = 0; n < 8; ++n)
#pragma unroll
        for (int q = 0; q < 4; ++q) O[n][q] = 0.f;
    float dl = 0.f, dh = 0.f;

    for (int tile = 0; tile < 64; ++tile) {
        int cur = tile & 1;
        if (tile < 63) {
            load_kv(sb + (uint32_t)(cur ^ 1) * STAGEB, b, (tile + 1) * 64, t);
            CPA_COMMIT();
            CPA_WAIT1();
        } else {
            CPA_WAIT0();
        }
        __syncthreads();

        const uint32_t bB = sb + (uint32_t)cur * STAGEB + offB;

        // ---- S = Qhi Khi^T + Qlo Khi^T + Qhi Klo^T  (fp32 accum)
        float S[8][4];
#pragma unroll
        for (int n = 0; n < 8; ++n)
#pragma unroll
            for (int q = 0; q < 4; ++q) S[n][q] = 0.f;

#pragma unroll
        for (int kb = 0; kb < 4; ++kb) {
#pragma unroll
            for (int np = 0; np < 4; ++np) {
                uint32_t bh[4], bl[4];
                ldsm4(bh, bB + KH + (uint32_t)(np * 16 * STRD * 2) + kb * 32);
                mma_bf16(S[np * 2],     qfh[kb], bh[0], bh[1]);
                mma_bf16(S[np * 2 + 1], qfh[kb], bh[2], bh[3]);
                mma_bf16(S[np * 2],     qfl[kb], bh[0], bh[1]);
                mma_bf16(S[np * 2 + 1], qfl[kb], bh[2], bh[3]);
                ldsm4(bl, bB + KL + (uint32_t)(np * 16 * STRD * 2) + kb * 32);
                mma_bf16(S[np * 2],     qfh[kb], bl[0], bl[1]);
                mma_bf16(S[np * 2 + 1], qfh[kb], bl[2], bl[3]);
            }
        }

        // ---- exp, row sums, hi/lo pack -> P fragments
        float rl = 0.f, rh = 0.f;
#pragma unroll
        for (int n = 0; n < 8; ++n) {
#pragma unroll
            for (int q = 0; q < 4; ++q) S[n][q] = __expf(S[n][q]);
            rl += S[n][0] + S[n][1];
            rh += S[n][2] + S[n][3];
        }
        dl += rl; dh += rh;

        uint32_t phi[4][4], plo[4][4];
#pragma unroll
        for (int jb = 0; jb < 4; ++jb) {
#pragma unroll
            for (int rp = 0; rp < 4; ++rp) {
                int n = jb * 2 + (rp >> 1);
                float e0 = S[n][(rp & 1) * 2 + 0];
                float e1 = S[n][(rp & 1) * 2 + 1];
                uint32_t hh;
                asm("cvt.rn.bf16x2.f32 %0, %1, %2;" : "=r"(hh) : "f"(e1), "f"(e0));
                phi[jb][rp] = hh;
                float l0 = e0 - __uint_as_float(hh << 16);
                float l1 = e1 - __uint_as_float(hh & 0xffff0000u);
                uint32_t ll;
                asm("cvt.rn.bf16x2.f32 %0, %1, %2;" : "=r"(ll) : "f"(l1), "f"(l0));
                plo[jb][rp] = ll;
            }
        }

        // ---- O += Phi Vhi + Plo Vhi + Phi Vlo
#pragma unroll
        for (int jb = 0; jb < 4; ++jb) {
#pragma unroll
            for (int vp = 0; vp < 4; ++vp) {
                uint32_t bh[4], bl[4];
                ldsm4(bh, bB + VH + (uint32_t)(vp * 16 * STRD * 2) + jb * 32);
                mma_bf16(O[vp * 2],     phi[jb], bh[0], bh[1]);
                mma_bf16(O[vp * 2 + 1], phi[jb], bh[2], bh[3]);
                mma_bf16(O[vp * 2],     plo[jb], bh[0], bh[1]);
                mma_bf16(O[vp * 2 + 1], plo[jb], bh[2], bh[3]);
                ldsm4(bl, bB + VL + (uint32_t)(vp * 16 * STRD * 2) + jb * 32);
                mma_bf16(O[vp * 2],     phi[jb], bl[0], bl[1]);
                mma_bf16(O[vp * 2 + 1], phi[jb], bl[2], bl[3]);
            }
        }
        __syncthreads();
    }

    // row-sum reduce across the 4 lanes of each row group
    dl += __shfl_xor_sync(0xffffffffu, dl, 1);
    dl += __shfl_xor_sync(0xffffffffu, dl, 2);
    dh += __shfl_xor_sync(0xffffffffu, dh, 1);
    dh += __shfl_xor_sync(0xffffffffu, dh, 2);
    float invl = 1.f / dl, invh = 1.f / dh;

    // ---- write out[b][v][i] via smem transpose (float [64][68] in stage 0)
    __syncthreads();
    float* Os = (float*)sm;
    {
        int ir = w * 16 + gid;
#pragma unroll
        for (int n = 0; n < 8; ++n) {
            int v0 = n * 8 + tig * 2;
            Os[v0 * 68 + ir]           = O[n][0] * invl;
            Os[(v0 + 1) * 68 + ir]     = O[n][1] * invl;
            Os[v0 * 68 + ir + 8]       = O[n][2] * invh;
            Os[(v0 + 1) * 68 + ir + 8] = O[n][3] * invh;
        }
    }
    __syncthreads();
    {
        int v = t >> 1, hc = (t & 1) * 32;
        float* dst = out + ((size_t)b * 64 + v) * L + i0 + hc;
        const float* srcp = Os + v * 68 + hc;
#pragma unroll
        for (int c = 0; c < 8; ++c)
            *(float4*)(dst + c * 4) = *(const float4*)(srcp + c * 4);
    }
}

// ---------------- launch ----------------
extern "C" void kernel_launch(void* const* d_in, const int* in_sizes, int n_in,
                              void* d_out, int out_size) {
    const float* x     = (const float*)d_in[0];
    const float* x_enc = (const float*)d_in[1];
    const float* Wq    = (const float*)d_in[2];
    const float* bq    = (const float*)d_in[3];
    const float* Wk    = (const float*)d_in[4];
    const float* bk    = (const float*)d_in[5];
    const float* Wv    = (const float*)d_in[6];
    const float* bv    = (const float*)d_in[7];
    float* out = (float*)d_out;

    prep_w_kernel<<<(64 * CENC_P + 255) / 256, 256>>>(Wq, CENC, CENC_P, 0);
    prep_w_kernel<<<(64 * CENC_P + 255) / 256, 256>>>(Wk, CENC, CENC_P, 1);
    prep_w_kernel<<<(64 * CIN_P  + 255) / 256, 256>>>(Wv, CIN,  CIN_P,  2);

    proj_kernel<<<dim3(L / 64, B, 3), 128, 17408>>>(x, x_enc, bq, bk, bv);

    static bool attr_set = false;
    if (!attr_set) {
        cudaFuncSetAttribute(attn_kernel, cudaFuncAttributeMaxDynamicSharedMemorySize,
                             2 * STAGEB);
        attr_set = true;
    }
    attn_kernel<<<dim3(L / 64, B), 128, 2 * STAGEB>>>(out);
}

// round 7
// speedup vs baseline: 6.8965x; 1.6427x over previous
#include <cuda_runtime.h>
#include <cuda_bf16.h>
#include <math.h>
#include <stdint.h>

#define B    2
#define CIN  320
#define CENC 326
#define L    4096

#define CENC_P 336   // padded to multiple of 16
#define CIN_P  320

#define STRD 72      // bf16 row stride in attention smem tiles (144B, 16B-aligned)
#define WST  24      // bf16 row stride in proj smem tiles (48B rows)

#define SPLIT 2
#define JSPAN (L / SPLIT)    // 2048
#define NTILE (JSPAN / 64)   // 32

// ---------------- scratch (device globals) ----------------
__device__ __nv_bfloat16 g_Qhi[B * L * 64];
__device__ __nv_bfloat16 g_Khi[B * L * 64];
__device__ __nv_bfloat16 g_Vthi[B * 64 * L], g_Vtlo[B * 64 * L];   // [b][v][l]
__device__ __nv_bfloat16 g_Whq[64 * CENC_P], g_Wlq[64 * CENC_P];   // [d][c] hi/lo
__device__ __nv_bfloat16 g_Whk[64 * CENC_P], g_Wlk[64 * CENC_P];
__device__ __nv_bfloat16 g_Whv[64 * CIN_P],  g_Wlv[64 * CIN_P];
__device__ float g_pO[SPLIT][B * 64 * L];    // partial O, [sp][b][v][i]
__device__ float g_pd[SPLIT][B * L];         // partial denominators

// ---------------- helpers ----------------
__device__ __forceinline__ uint32_t smem_u32(const void* p) {
    uint32_t a;
    asm("{ .reg .u64 t; cvta.to.shared.u64 t, %1; cvt.u32.u64 %0, t; }" : "=r"(a) : "l"(p));
    return a;
}
__device__ __forceinline__ void ldsm4(uint32_t r[4], uint32_t addr) {
    asm volatile("ldmatrix.sync.aligned.m8n8.x4.shared.b16 {%0,%1,%2,%3}, [%4];"
        : "=r"(r[0]), "=r"(r[1]), "=r"(r[2]), "=r"(r[3]) : "r"(addr));
}
__device__ __forceinline__ void mma_bf16(float c[4], const uint32_t a[4],
                                         uint32_t b0, uint32_t b1) {
    asm volatile("mma.sync.aligned.m16n8k16.row.col.f32.bf16.bf16.f32 "
        "{%0,%1,%2,%3}, {%4,%5,%6,%7}, {%8,%9}, {%0,%1,%2,%3};"
        : "+f"(c[0]), "+f"(c[1]), "+f"(c[2]), "+f"(c[3])
        : "r"(a[0]), "r"(a[1]), "r"(a[2]), "r"(a[3]), "r"(b0), "r"(b1));
}
__device__ __forceinline__ void cpa16(uint32_t dst, const void* src) {
    asm volatile("cp.async.cg.shared.global [%0], [%1], 16;" :: "r"(dst), "l"(src));
}
#define CPA_COMMIT() asm volatile("cp.async.commit_group;" ::: "memory")
#define CPA_WAIT1()  asm volatile("cp.async.wait_group 1;" ::: "memory")
#define CPA_WAIT0()  asm volatile("cp.async.wait_group 0;" ::: "memory")

// ---------------- weight prep: W[d][c] fp32 -> bf16 hi/lo [d][Cpad] ----------------
__global__ void prep_w_kernel(const float* __restrict__ W, int Cdim, int Cpad, int which) {
    __nv_bfloat16* Wh = (which == 0) ? g_Whq : (which == 1) ? g_Whk : g_Whv;
    __nv_bfloat16* Wl = (which == 0) ? g_Wlq : (which == 1) ? g_Wlk : g_Wlv;
    int idx = blockIdx.x * blockDim.x + threadIdx.x;
    if (idx < 64 * Cpad) {
        int d = idx / Cpad, c = idx - d * Cpad;
        float v = (c < Cdim) ? W[d * Cdim + c] : 0.f;
        __nv_bfloat16 h = __float2bfloat16(v);
        Wh[idx] = h;
        Wl[idx] = __float2bfloat16(v - __bfloat162float(h));
    }
}

// ---------------- tensor-core projections ----------------
// grid (L/64, B, 3), 128 threads. out[64 d][64 l] = W[64][C] @ X[C][64-l-tile]
// smem: 4 bf16 tiles [64][WST] = 3072B each: Xh @0, Xl @3072, Whs @6144, Wls @9216
__global__ __launch_bounds__(128) void proj_kernel(const float* __restrict__ x,
                                                   const float* __restrict__ x_enc,
                                                   const float* __restrict__ bq,
                                                   const float* __restrict__ bk,
                                                   const float* __restrict__ bv) {
    int z = blockIdx.z, b = blockIdx.y, l0 = blockIdx.x * 64;
    const float* src  = (z == 2) ? x : x_enc;
    const __nv_bfloat16* Wh = (z == 0) ? g_Whq : (z == 1) ? g_Whk : g_Whv;
    const __nv_bfloat16* Wl = (z == 0) ? g_Wlq : (z == 1) ? g_Wlk : g_Wlv;
    const float* bias = (z == 0) ? bq : (z == 1) ? bk : bv;
    int Cdim = (z == 2) ? CIN : CENC;
    int Cpad = (z == 2) ? CIN_P : CENC_P;

    extern __shared__ char psm[];
    __nv_bfloat16* Xh  = (__nv_bfloat16*)(psm);
    __nv_bfloat16* Xl  = (__nv_bfloat16*)(psm + 3072);
    __nv_bfloat16* Whs = (__nv_bfloat16*)(psm + 6144);
    __nv_bfloat16* Wls = (__nv_bfloat16*)(psm + 9216);
    __shared__ float nrmA[64];
    uint32_t sb = smem_u32(psm);

    int t = threadIdx.x, lane = t & 31, w = t >> 5;
    int gid = lane >> 2, tig = lane & 3, lr = lane & 7, lg = lane >> 3;

    float S[8][4];
#pragma unroll
    for (int n = 0; n < 8; ++n)
#pragma unroll
        for (int q = 0; q < 4; ++q) S[n][q] = 0.f;

    const float* srcb = src + (size_t)b * Cdim * L + l0;
    const uint32_t offB = (uint32_t)(((lr + (lg >> 1) * 8) * WST + (lg & 1) * 8) * 2);
    const uint32_t bX = sb + offB;

    int nCh = Cpad / 16;

    // prefetch chunk 0 into registers
    float xv[8];
#pragma unroll
    for (int i = 0; i < 8; ++i) {
        int idx = t + i * 128;
        int c = idx >> 6, l = idx & 63;
        xv[i] = (c < Cdim) ? __ldg(srcb + (size_t)c * L + l) : 0.f;
    }

    for (int ch = 0; ch < nCh; ++ch) {
        int c0 = ch * 16;
        __syncthreads();
        // store converted X chunk from registers
#pragma unroll
        for (int i = 0; i < 8; ++i) {
            int idx = t + i * 128;
            int c = idx >> 6, l = idx & 63;
            __nv_bfloat16 h = __float2bfloat16(xv[i]);
            Xh[l * WST + c] = h;
            Xl[l * WST + c] = __float2bfloat16(xv[i] - __bfloat162float(h));
        }
        // stage W tile [64 d][16 c] hi/lo
#pragma unroll
        for (int i = 0; i < 4; ++i) {
            int idx = t + i * 128;
            int d = idx >> 3, cp = idx & 7;
            *(uint32_t*)&Whs[d * WST + cp * 2] = *(const uint32_t*)&Wh[d * Cpad + c0 + cp * 2];
            *(uint32_t*)&Wls[d * WST + cp * 2] = *(const uint32_t*)&Wl[d * Cpad + c0 + cp * 2];
        }
        __syncthreads();

        // prefetch next chunk (LDG latency hides behind the mma block below)
        if (ch + 1 < nCh) {
            int c1 = (ch + 1) * 16;
#pragma unroll
            for (int i = 0; i < 8; ++i) {
                int idx = t + i * 128;
                int c = c1 + (idx >> 6), l = idx & 63;
                xv[i] = (c < Cdim) ? __ldg(srcb + (size_t)c * L + l) : 0.f;
            }
        }

        // A fragments (W rows w*16..w*16+15, k = 16) via direct LDS.32
        uint32_t ah[4], al[4];
        {
            int r0 = (w * 16 + gid) * WST, r8 = (w * 16 + gid + 8) * WST;
            ah[0] = *(const uint32_t*)&Whs[r0 + tig * 2];
            ah[1] = *(const uint32_t*)&Whs[r8 + tig * 2];
            ah[2] = *(const uint32_t*)&Whs[r0 + tig * 2 + 8];
            ah[3] = *(const uint32_t*)&Whs[r8 + tig * 2 + 8];
            al[0] = *(const uint32_t*)&Wls[r0 + tig * 2];
            al[1] = *(const uint32_t*)&Wls[r8 + tig * 2];
            al[2] = *(const uint32_t*)&Wls[r0 + tig * 2 + 8];
            al[3] = *(const uint32_t*)&Wls[r8 + tig * 2 + 8];
        }

#pragma unroll
        for (int np = 0; np < 4; ++np) {
            uint32_t bh[4], bl[4];
            ldsm4(bh, bX + (uint32_t)(np * 16 * WST * 2));
            mma_bf16(S[np * 2],     ah, bh[0], bh[1]);
            mma_bf16(S[np * 2 + 1], ah, bh[2], bh[3]);
            mma_bf16(S[np * 2],     al, bh[0], bh[1]);
            mma_bf16(S[np * 2 + 1], al, bh[2], bh[3]);
            ldsm4(bl, bX + 3072u + (uint32_t)(np * 16 * WST * 2));
            mma_bf16(S[np * 2],     ah, bl[0], bl[1]);
            mma_bf16(S[np * 2 + 1], ah, bl[2], bl[3]);
        }
    }

    float b0v = __ldg(bias + w * 16 + gid);
    float b8v = __ldg(bias + w * 16 + gid + 8);

    float* Osm = (float*)psm;   // [64][68] floats = 17408B
    __syncthreads();

    if (z < 2) {
        // write [l][d] with bias
#pragma unroll
        for (int n = 0; n < 8; ++n) {
            int lc = n * 8 + tig * 2, d0 = w * 16 + gid;
            Osm[lc * 68 + d0]           = S[n][0] + b0v;
            Osm[(lc + 1) * 68 + d0]     = S[n][1] + b0v;
            Osm[lc * 68 + d0 + 8]       = S[n][2] + b8v;
            Osm[(lc + 1) * 68 + d0 + 8] = S[n][3] + b8v;
        }
        __syncthreads();
        if (t < 64) {
            float ss = 0.f;
#pragma unroll
            for (int d = 0; d < 64; ++d) { float v = Osm[t * 68 + d]; ss += v * v; }
            nrmA[t] = 1.f / fmaxf(sqrtf(ss), 1e-6f);
        }
        __syncthreads();
        __nv_bfloat16* dh = (z == 0) ? g_Qhi : g_Khi;
        int l = t & 63, dg = t >> 6;              // 32 d's per thread
        float sc = nrmA[l];
        size_t obase = ((size_t)b * L + l0 + l) * 64 + dg * 32;
#pragma unroll
        for (int i = 0; i < 8; ++i) {
            __nv_bfloat16 th[4];
#pragma unroll
            for (int k = 0; k < 4; ++k)
                th[k] = __float2bfloat16(Osm[l * 68 + dg * 32 + i * 4 + k] * sc);
            *(uint2*)&dh[obase + i * 4] = *(uint2*)th;
        }
    } else {
        // V: write [d][l] with bias, then store transposed [v][l] hi/lo
#pragma unroll
        for (int n = 0; n < 8; ++n) {
            int lc = n * 8 + tig * 2, d0 = w * 16 + gid;
            Osm[d0 * 68 + lc]           = S[n][0] + b0v;
            Osm[d0 * 68 + lc + 1]       = S[n][1] + b0v;
            Osm[(d0 + 8) * 68 + lc]     = S[n][2] + b8v;
            Osm[(d0 + 8) * 68 + lc + 1] = S[n][3] + b8v;
        }
        __syncthreads();
        int v = t >> 1, half = t & 1;
        size_t obase = ((size_t)b * 64 + v) * L + l0 + half * 32;
#pragma unroll
        for (int i = 0; i < 8; ++i) {
            __nv_bfloat16 th[4], tl[4];
#pragma unroll
            for (int k = 0; k < 4; ++k) {
                float vv = Osm[v * 68 + half * 32 + i * 4 + k];
                th[k] = __float2bfloat16(vv);
                tl[k] = __float2bfloat16(vv - __bfloat162float(th[k]));
            }
            *(uint2*)&g_Vthi[obase + i * 4] = *(uint2*)th;
            *(uint2*)&g_Vtlo[obase + i * 4] = *(uint2*)tl;
        }
    }
}

// ---------------- mma.sync flash attention (split-j, cp.async double-buffered) ----
// grid (L/64, B, SPLIT), 128 threads (4 warps), warp w owns query rows w*16..w*16+15.
#define KHO 0u
#define VHO 9216u
#define VLO 18432u
#define STAGEB 27648u

__device__ __forceinline__ void load_kv(uint32_t sbase, int b, int j0, int t) {
#pragma unroll
    for (int i = 0; i < 4; ++i) {
        int idx = t + i * 128;
        int r = idx >> 3, c = idx & 7;
        uint32_t so = (uint32_t)((r * STRD + c * 8) * 2);
        size_t kg = ((size_t)b * L + j0 + r) * 64 + c * 8;
        cpa16(sbase + KHO + so, g_Khi + kg);
        size_t vg = ((size_t)b * 64 + r) * L + j0 + c * 8;
        cpa16(sbase + VHO + so, g_Vthi + vg);
        cpa16(sbase + VLO + so, g_Vtlo + vg);
    }
}

__global__ __launch_bounds__(128) void attn_kernel() {
    extern __shared__ char sm[];
    const uint32_t sb = smem_u32(sm);
    const int t = threadIdx.x, lane = t & 31, w = t >> 5;
    const int b = blockIdx.y, i0 = blockIdx.x * 64, sp = blockIdx.z;
    const int jbase = sp * JSPAN;
    const int gid = lane >> 2, tig = lane & 3;
    const int lr = lane & 7, lg = lane >> 3;

    const uint32_t offA = (uint32_t)(((lr + ((lg & 1) << 3)) * STRD + ((lg >> 1) << 3)) * 2);
    const uint32_t offB = (uint32_t)(((lr + ((lg >> 1) << 3)) * STRD + ((lg & 1) << 3)) * 2);

    // ---- stage Q (hi) into stage-0, build persistent A fragments
    {
        const uint4* qh = (const uint4*)(g_Qhi + ((size_t)b * L + i0) * 64);
        for (int idx = t; idx < 512; idx += 128) {
            int r = idx >> 3, c = idx & 7;
            uint32_t so = (uint32_t)((r * STRD + c * 8) * 2);
            *(uint4*)(sm + so) = qh[idx];
        }
    }
    __syncthreads();
    uint32_t qfh[4][4];
    {
        uint32_t base = sb + (uint32_t)(w * 16 * STRD * 2) + offA;
#pragma unroll
        for (int kb = 0; kb < 4; ++kb) ldsm4(qfh[kb], base + kb * 32);
    }
    __syncthreads();

    // prologue: async-load tile 0 into stage 0
    load_kv(sb, b, jbase, t);
    CPA_COMMIT();

    float O[8][4];
#pragma unroll
    for (int n = 0; n < 8; ++n)
#pragma unroll
        for (int q = 0; q < 4; ++q) O[n][q] = 0.f;
    float dl = 0.f, dh = 0.f;

    for (int tile = 0; tile < NTILE; ++tile) {
        int cur = tile & 1;
        if (tile < NTILE - 1) {
            load_kv(sb + (uint32_t)(cur ^ 1) * STAGEB, b, jbase + (tile + 1) * 64, t);
            CPA_COMMIT();
            CPA_WAIT1();
        } else {
            CPA_WAIT0();
        }
        __syncthreads();

        const uint32_t bB = sb + (uint32_t)cur * STAGEB + offB;

        // ---- S = Qhi Khi^T (single pass, fp32 accum)
        float S[8][4];
#pragma unroll
        for (int n = 0; n < 8; ++n)
#pragma unroll
            for (int q = 0; q < 4; ++q) S[n][q] = 0.f;

#pragma unroll
        for (int kb = 0; kb < 4; ++kb) {
#pragma unroll
            for (int np = 0; np < 4; ++np) {
                uint32_t bh[4];
                ldsm4(bh, bB + KHO + (uint32_t)(np * 16 * STRD * 2) + kb * 32);
                mma_bf16(S[np * 2],     qfh[kb], bh[0], bh[1]);
                mma_bf16(S[np * 2 + 1], qfh[kb], bh[2], bh[3]);
            }
        }

        // ---- exp, row sums, hi/lo pack -> P fragments
        float rl = 0.f, rh = 0.f;
#pragma unroll
        for (int n = 0; n < 8; ++n) {
#pragma unroll
            for (int q = 0; q < 4; ++q) S[n][q] = __expf(S[n][q]);
            rl += S[n][0] + S[n][1];
            rh += S[n][2] + S[n][3];
        }
        dl += rl; dh += rh;

        uint32_t phi[4][4], plo[4][4];
#pragma unroll
        for (int jb = 0; jb < 4; ++jb) {
#pragma unroll
            for (int rp = 0; rp < 4; ++rp) {
                int n = jb * 2 + (rp >> 1);
                float e0 = S[n][(rp & 1) * 2 + 0];
                float e1 = S[n][(rp & 1) * 2 + 1];
                uint32_t hh;
                asm("cvt.rn.bf16x2.f32 %0, %1, %2;" : "=r"(hh) : "f"(e1), "f"(e0));
                phi[jb][rp] = hh;
                float l0 = e0 - __uint_as_float(hh << 16);
                float l1 = e1 - __uint_as_float(hh & 0xffff0000u);
                uint32_t ll;
                asm("cvt.rn.bf16x2.f32 %0, %1, %2;" : "=r"(ll) : "f"(l1), "f"(l0));
                plo[jb][rp] = ll;
            }
        }

        // ---- O += Phi Vhi + Plo Vhi + Phi Vlo
#pragma unroll
        for (int jb = 0; jb < 4; ++jb) {
#pragma unroll
            for (int vp = 0; vp < 4; ++vp) {
                uint32_t bh[4], bl[4];
                ldsm4(bh, bB + VHO + (uint32_t)(vp * 16 * STRD * 2) + jb * 32);
                mma_bf16(O[vp * 2],     phi[jb], bh[0], bh[1]);
                mma_bf16(O[vp * 2 + 1], phi[jb], bh[2], bh[3]);
                mma_bf16(O[vp * 2],     plo[jb], bh[0], bh[1]);
                mma_bf16(O[vp * 2 + 1], plo[jb], bh[2], bh[3]);
                ldsm4(bl, bB + VLO + (uint32_t)(vp * 16 * STRD * 2) + jb * 32);
                mma_bf16(O[vp * 2],     phi[jb], bl[0], bl[1]);
                mma_bf16(O[vp * 2 + 1], phi[jb], bl[2], bl[3]);
            }
        }
        __syncthreads();
    }

    // row-sum reduce across the 4 lanes of each row group; store partial denoms
    dl += __shfl_xor_sync(0xffffffffu, dl, 1);
    dl += __shfl_xor_sync(0xffffffffu, dl, 2);
    dh += __shfl_xor_sync(0xffffffffu, dh, 1);
    dh += __shfl_xor_sync(0xffffffffu, dh, 2);
    if (tig == 0) {
        g_pd[sp][(size_t)b * L + i0 + w * 16 + gid]     = dl;
        g_pd[sp][(size_t)b * L + i0 + w * 16 + gid + 8] = dh;
    }

    // ---- write partial O (un-normalized) in [v][i] layout via smem transpose
    __syncthreads();
    float* Os = (float*)sm;
    {
        int ir = w * 16 + gid;
#pragma unroll
        for (int n = 0; n < 8; ++n) {
            int v0 = n * 8 + tig * 2;
            Os[v0 * 68 + ir]           = O[n][0];
            Os[(v0 + 1) * 68 + ir]     = O[n][1];
            Os[v0 * 68 + ir + 8]       = O[n][2];
            Os[(v0 + 1) * 68 + ir + 8] = O[n][3];
        }
    }
    __syncthreads();
    {
        int v = t >> 1, hc = (t & 1) * 32;
        float* dst = g_pO[sp] + ((size_t)b * 64 + v) * L + i0 + hc;
        const float* srcp = Os + v * 68 + hc;
#pragma unroll
        for (int c = 0; c < 8; ++c)
            *(float4*)(dst + c * 4) = *(const float4*)(srcp + c * 4);
    }
}

// ---------------- combine: out[b][v][i] = (O0+O1)/(d0+d1) ----------------
__global__ __launch_bounds__(256) void combine_kernel(float* __restrict__ out) {
    int e0 = (blockIdx.x * 256 + threadIdx.x) * 8;   // element index into [b][v][i]
    int b = e0 >> 18;               // / (64*L)
    int i = e0 & (L - 1);
    float4 d0a = *(const float4*)&g_pd[0][(size_t)b * L + i];
    float4 d0b = *(const float4*)&g_pd[0][(size_t)b * L + i + 4];
    float4 d1a = *(const float4*)&g_pd[1][(size_t)b * L + i];
    float4 d1b = *(const float4*)&g_pd[1][(size_t)b * L + i + 4];
    float4 p0a = *(const float4*)&g_pO[0][e0];
    float4 p0b = *(const float4*)&g_pO[0][e0 + 4];
    float4 p1a = *(const float4*)&g_pO[1][e0];
    float4 p1b = *(const float4*)&g_pO[1][e0 + 4];
    float4 oa, ob;
    oa.x = (p0a.x + p1a.x) / (d0a.x + d1a.x);
    oa.y = (p0a.y + p1a.y) / (d0a.y + d1a.y);
    oa.z = (p0a.z + p1a.z) / (d0a.z + d1a.z);
    oa.w = (p0a.w + p1a.w) / (d0a.w + d1a.w);
    ob.x = (p0b.x + p1b.x) / (d0b.x + d1b.x);
    ob.y = (p0b.y + p1b.y) / (d0b.y + d1b.y);
    ob.z = (p0b.z + p1b.z) / (d0b.z + d1b.z);
    ob.w = (p0b.w + p1b.w) / (d0b.w + d1b.w);
    *(float4*)&out[e0]     = oa;
    *(float4*)&out[e0 + 4] = ob;
}

// ---------------- launch ----------------
extern "C" void kernel_launch(void* const* d_in, const int* in_sizes, int n_in,
                              void* d_out, int out_size) {
    const float* x     = (const float*)d_in[0];
    const float* x_enc = (const float*)d_in[1];
    const float* Wq    = (const float*)d_in[2];
    const float* bq    = (const float*)d_in[3];
    const float* Wk    = (const float*)d_in[4];
    const float* bk    = (const float*)d_in[5];
    const float* Wv    = (const float*)d_in[6];
    const float* bv    = (const float*)d_in[7];
    float* out = (float*)d_out;

    prep_w_kernel<<<(64 * CENC_P + 255) / 256, 256>>>(Wq, CENC, CENC_P, 0);
    prep_w_kernel<<<(64 * CENC_P + 255) / 256, 256>>>(Wk, CENC, CENC_P, 1);
    prep_w_kernel<<<(64 * CIN_P  + 255) / 256, 256>>>(Wv, CIN,  CIN_P,  2);

    proj_kernel<<<dim3(L / 64, B, 3), 128, 17408>>>(x, x_enc, bq, bk, bv);

    static bool attr_set = false;
    if (!attr_set) {
        cudaFuncSetAttribute(attn_kernel, cudaFuncAttributeMaxDynamicSharedMemorySize,
                             2 * STAGEB);
        attr_set = true;
    }
    attn_kernel<<<dim3(L / 64, B, SPLIT), 128, 2 * STAGEB>>>();

    combine_kernel<<<(B * 64 * L) / (256 * 8), 256>>>(out);
}

// round 8
// speedup vs baseline: 7.6638x; 1.1113x over previous
#include <cuda_runtime.h>
#include <cuda_bf16.h>
#include <math.h>
#include <stdint.h>

#define B    2
#define CIN  320
#define CENC 326
#define L    4096

#define CENC_P 336   // padded to multiple of 16
#define CIN_P  320

#define STRD 72      // bf16 row stride in attention smem tiles (144B, 16B-aligned)
#define WST  24      // bf16 row stride in proj smem tiles (48B rows)

#define SPLIT 4
#define JSPAN (L / SPLIT)    // 1024
#define NTILE (JSPAN / 64)   // 16
#define MQ    128            // queries per CTA (32 rows per warp, 2 m-groups)

// ---------------- scratch (device globals) ----------------
__device__ __nv_bfloat16 g_Qhi[B * L * 64];
__device__ __nv_bfloat16 g_Khi[B * L * 64];
__device__ __nv_bfloat16 g_Vthi[B * 64 * L], g_Vtlo[B * 64 * L];   // [b][v][l]
__device__ __nv_bfloat16 g_Whq[64 * CENC_P], g_Wlq[64 * CENC_P];   // [d][c] hi/lo
__device__ __nv_bfloat16 g_Whk[64 * CENC_P], g_Wlk[64 * CENC_P];
__device__ __nv_bfloat16 g_Whv[64 * CIN_P],  g_Wlv[64 * CIN_P];
__device__ float g_pO[SPLIT][B * 64 * L];    // partial O, [sp][b][v][i]
__device__ float g_pd[SPLIT][B * L];         // partial denominators

// ---------------- helpers ----------------
__device__ __forceinline__ uint32_t smem_u32(const void* p) {
    uint32_t a;
    asm("{ .reg .u64 t; cvta.to.shared.u64 t, %1; cvt.u32.u64 %0, t; }" : "=r"(a) : "l"(p));
    return a;
}
__device__ __forceinline__ void ldsm4(uint32_t r[4], uint32_t addr) {
    asm volatile("ldmatrix.sync.aligned.m8n8.x4.shared.b16 {%0,%1,%2,%3}, [%4];"
        : "=r"(r[0]), "=r"(r[1]), "=r"(r[2]), "=r"(r[3]) : "r"(addr));
}
__device__ __forceinline__ void mma_bf16(float c[4], const uint32_t a[4],
                                         uint32_t b0, uint32_t b1) {
    asm volatile("mma.sync.aligned.m16n8k16.row.col.f32.bf16.bf16.f32 "
        "{%0,%1,%2,%3}, {%4,%5,%6,%7}, {%8,%9}, {%0,%1,%2,%3};"
        : "+f"(c[0]), "+f"(c[1]), "+f"(c[2]), "+f"(c[3])
        : "r"(a[0]), "r"(a[1]), "r"(a[2]), "r"(a[3]), "r"(b0), "r"(b1));
}
__device__ __forceinline__ void cpa16(uint32_t dst, const void* src) {
    asm volatile("cp.async.cg.shared.global [%0], [%1], 16;" :: "r"(dst), "l"(src));
}
#define CPA_COMMIT() asm volatile("cp.async.commit_group;" ::: "memory")
#define CPA_WAIT1()  asm volatile("cp.async.wait_group 1;" ::: "memory")
#define CPA_WAIT0()  asm volatile("cp.async.wait_group 0;" ::: "memory")

// ---------------- weight prep: W[d][c] fp32 -> bf16 hi/lo [d][Cpad] ----------------
__global__ void prep_w_kernel(const float* __restrict__ W, int Cdim, int Cpad, int which) {
    __nv_bfloat16* Wh = (which == 0) ? g_Whq : (which == 1) ? g_Whk : g_Whv;
    __nv_bfloat16* Wl = (which == 0) ? g_Wlq : (which == 1) ? g_Wlk : g_Wlv;
    int idx = blockIdx.x * blockDim.x + threadIdx.x;
    if (idx < 64 * Cpad) {
        int d = idx / Cpad, c = idx - d * Cpad;
        float v = (c < Cdim) ? W[d * Cdim + c] : 0.f;
        __nv_bfloat16 h = __float2bfloat16(v);
        Wh[idx] = h;
        Wl[idx] = __float2bfloat16(v - __bfloat162float(h));
    }
}

// ---------------- tensor-core projections (Q+K fused; V separate) ----------------
// grid (L/64, B, 2), 128 threads. z=0: Q and K from x_enc; z=1: V from x.
// smem bf16 tiles [64][WST]=3072B: Xh@0, Xl@3072, W0h@6144, W0l@9216, W1h@12288, W1l@15360
__global__ __launch_bounds__(128) void proj_kernel(const float* __restrict__ x,
                                                   const float* __restrict__ x_enc,
                                                   const float* __restrict__ bq,
                                                   const float* __restrict__ bk,
                                                   const float* __restrict__ bv) {
    int z = blockIdx.z, b = blockIdx.y, l0 = blockIdx.x * 64;
    bool qk = (z == 0);
    const float* src = qk ? x_enc : x;
    const __nv_bfloat16* W0h = qk ? g_Whq : g_Whv;
    const __nv_bfloat16* W0l = qk ? g_Wlq : g_Wlv;
    int Cdim = qk ? CENC : CIN;
    int Cpad = qk ? CENC_P : CIN_P;

    extern __shared__ char psm[];
    __nv_bfloat16* Xh  = (__nv_bfloat16*)(psm);
    __nv_bfloat16* Xl  = (__nv_bfloat16*)(psm + 3072);
    __nv_bfloat16* Ws0h = (__nv_bfloat16*)(psm + 6144);
    __nv_bfloat16* Ws0l = (__nv_bfloat16*)(psm + 9216);
    __nv_bfloat16* Ws1h = (__nv_bfloat16*)(psm + 12288);
    __nv_bfloat16* Ws1l = (__nv_bfloat16*)(psm + 15360);
    __shared__ float nrmA[64];
    uint32_t sb = smem_u32(psm);

    int t = threadIdx.x, lane = t & 31, w = t >> 5;
    int gid = lane >> 2, tig = lane & 3, lr = lane & 7, lg = lane >> 3;

    float Sq[8][4], Sk[8][4];
#pragma unroll
    for (int n = 0; n < 8; ++n)
#pragma unroll
        for (int q = 0; q < 4; ++q) { Sq[n][q] = 0.f; Sk[n][q] = 0.f; }

    const float* srcb = src + (size_t)b * Cdim * L + l0;
    const uint32_t offB = (uint32_t)(((lr + (lg >> 1) * 8) * WST + (lg & 1) * 8) * 2);
    const uint32_t bX = sb + offB;

    int nCh = Cpad / 16;

    float xv[8];
#pragma unroll
    for (int i = 0; i < 8; ++i) {
        int idx = t + i * 128;
        int c = idx >> 6, l = idx & 63;
        xv[i] = (c < Cdim) ? __ldg(srcb + (size_t)c * L + l) : 0.f;
    }

    for (int ch = 0; ch < nCh; ++ch) {
        int c0 = ch * 16;
        __syncthreads();
#pragma unroll
        for (int i = 0; i < 8; ++i) {
            int idx = t + i * 128;
            int c = idx >> 6, l = idx & 63;
            __nv_bfloat16 h = __float2bfloat16(xv[i]);
            Xh[l * WST + c] = h;
            Xl[l * WST + c] = __float2bfloat16(xv[i] - __bfloat162float(h));
        }
#pragma unroll
        for (int i = 0; i < 4; ++i) {
            int idx = t + i * 128;
            int d = idx >> 3, cp = idx & 7;
            *(uint32_t*)&Ws0h[d * WST + cp * 2] = *(const uint32_t*)&W0h[d * Cpad + c0 + cp * 2];
            *(uint32_t*)&Ws0l[d * WST + cp * 2] = *(const uint32_t*)&W0l[d * Cpad + c0 + cp * 2];
        }
        if (qk) {
#pragma unroll
            for (int i = 0; i < 4; ++i) {
                int idx = t + i * 128;
                int d = idx >> 3, cp = idx & 7;
                *(uint32_t*)&Ws1h[d * WST + cp * 2] = *(const uint32_t*)&g_Whk[d * Cpad + c0 + cp * 2];
                *(uint32_t*)&Ws1l[d * WST + cp * 2] = *(const uint32_t*)&g_Wlk[d * Cpad + c0 + cp * 2];
            }
        }
        __syncthreads();

        if (ch + 1 < nCh) {
            int c1 = (ch + 1) * 16;
#pragma unroll
            for (int i = 0; i < 8; ++i) {
                int idx = t + i * 128;
                int c = c1 + (idx >> 6), l = idx & 63;
                xv[i] = (c < Cdim) ? __ldg(srcb + (size_t)c * L + l) : 0.f;
            }
        }

        uint32_t a0h[4], a0l[4], a1h[4], a1l[4];
        {
            int r0 = (w * 16 + gid) * WST, r8 = (w * 16 + gid + 8) * WST;
            a0h[0] = *(const uint32_t*)&Ws0h[r0 + tig * 2];
            a0h[1] = *(const uint32_t*)&Ws0h[r8 + tig * 2];
            a0h[2] = *(const uint32_t*)&Ws0h[r0 + tig * 2 + 8];
            a0h[3] = *(const uint32_t*)&Ws0h[r8 + tig * 2 + 8];
            a0l[0] = *(const uint32_t*)&Ws0l[r0 + tig * 2];
            a0l[1] = *(const uint32_t*)&Ws0l[r8 + tig * 2];
            a0l[2] = *(const uint32_t*)&Ws0l[r0 + tig * 2 + 8];
            a0l[3] = *(const uint32_t*)&Ws0l[r8 + tig * 2 + 8];
            if (qk) {
                a1h[0] = *(const uint32_t*)&Ws1h[r0 + tig * 2];
                a1h[1] = *(const uint32_t*)&Ws1h[r8 + tig * 2];
                a1h[2] = *(const uint32_t*)&Ws1h[r0 + tig * 2 + 8];
                a1h[3] = *(const uint32_t*)&Ws1h[r8 + tig * 2 + 8];
                a1l[0] = *(const uint32_t*)&Ws1l[r0 + tig * 2];
                a1l[1] = *(const uint32_t*)&Ws1l[r8 + tig * 2];
                a1l[2] = *(const uint32_t*)&Ws1l[r0 + tig * 2 + 8];
                a1l[3] = *(const uint32_t*)&Ws1l[r8 + tig * 2 + 8];
            }
        }

#pragma unroll
        for (int np = 0; np < 4; ++np) {
            uint32_t bh[4], bl[4];
            ldsm4(bh, bX + (uint32_t)(np * 16 * WST * 2));
            ldsm4(bl, bX + 3072u + (uint32_t)(np * 16 * WST * 2));
            mma_bf16(Sq[np * 2],     a0h, bh[0], bh[1]);
            mma_bf16(Sq[np * 2 + 1], a0h, bh[2], bh[3]);
            mma_bf16(Sq[np * 2],     a0l, bh[0], bh[1]);
            mma_bf16(Sq[np * 2 + 1], a0l, bh[2], bh[3]);
            mma_bf16(Sq[np * 2],     a0h, bl[0], bl[1]);
            mma_bf16(Sq[np * 2 + 1], a0h, bl[2], bl[3]);
            if (qk) {
                mma_bf16(Sk[np * 2],     a1h, bh[0], bh[1]);
                mma_bf16(Sk[np * 2 + 1], a1h, bh[2], bh[3]);
                mma_bf16(Sk[np * 2],     a1l, bh[0], bh[1]);
                mma_bf16(Sk[np * 2 + 1], a1l, bh[2], bh[3]);
                mma_bf16(Sk[np * 2],     a1h, bl[0], bl[1]);
                mma_bf16(Sk[np * 2 + 1], a1h, bl[2], bl[3]);
            }
        }
    }

    float* Osm = (float*)psm;   // [64][68] floats = 17408B

    if (qk) {
        // ---- Q then K: bias, L2-norm, bf16 store [l][d]
#pragma unroll
        for (int pass = 0; pass < 2; ++pass) {
            const float* bias = pass ? bk : bq;
            float (*S)[4] = pass ? Sk : Sq;
            __nv_bfloat16* dst = pass ? g_Khi : g_Qhi;
            float b0v = __ldg(bias + w * 16 + gid);
            float b8v = __ldg(bias + w * 16 + gid + 8);
            __syncthreads();
#pragma unroll
            for (int n = 0; n < 8; ++n) {
                int lc = n * 8 + tig * 2, d0 = w * 16 + gid;
                Osm[lc * 68 + d0]           = S[n][0] + b0v;
                Osm[(lc + 1) * 68 + d0]     = S[n][1] + b0v;
                Osm[lc * 68 + d0 + 8]       = S[n][2] + b8v;
                Osm[(lc + 1) * 68 + d0 + 8] = S[n][3] + b8v;
            }
            __syncthreads();
            if (t < 64) {
                float ss = 0.f;
#pragma unroll
                for (int d = 0; d < 64; ++d) { float v = Osm[t * 68 + d]; ss += v * v; }
                nrmA[t] = 1.f / fmaxf(sqrtf(ss), 1e-6f);
            }
            __syncthreads();
            int l = t & 63, dg = t >> 6;
            float sc = nrmA[l];
            size_t obase = ((size_t)b * L + l0 + l) * 64 + dg * 32;
#pragma unroll
            for (int i = 0; i < 8; ++i) {
                __nv_bfloat16 th[4];
#pragma unroll
                for (int k = 0; k < 4; ++k)
                    th[k] = __float2bfloat16(Osm[l * 68 + dg * 32 + i * 4 + k] * sc);
                *(uint2*)&dst[obase + i * 4] = *(uint2*)th;
            }
        }
    } else {
        float b0v = __ldg(bv + w * 16 + gid);
        float b8v = __ldg(bv + w * 16 + gid + 8);
        __syncthreads();
#pragma unroll
        for (int n = 0; n < 8; ++n) {
            int lc = n * 8 + tig * 2, d0 = w * 16 + gid;
            Osm[d0 * 68 + lc]           = Sq[n][0] + b0v;
            Osm[d0 * 68 + lc + 1]       = Sq[n][1] + b0v;
            Osm[(d0 + 8) * 68 + lc]     = Sq[n][2] + b8v;
            Osm[(d0 + 8) * 68 + lc + 1] = Sq[n][3] + b8v;
        }
        __syncthreads();
        int v = t >> 1, half = t & 1;
        size_t obase = ((size_t)b * 64 + v) * L + l0 + half * 32;
#pragma unroll
        for (int i = 0; i < 8; ++i) {
            __nv_bfloat16 th[4], tl[4];
#pragma unroll
            for (int k = 0; k < 4; ++k) {
                float vv = Osm[v * 68 + half * 32 + i * 4 + k];
                th[k] = __float2bfloat16(vv);
                tl[k] = __float2bfloat16(vv - __bfloat162float(th[k]));
            }
            *(uint2*)&g_Vthi[obase + i * 4] = *(uint2*)th;
            *(uint2*)&g_Vtlo[obase + i * 4] = *(uint2*)tl;
        }
    }
}

// ---------------- mma.sync flash attention (MQ=128, split-j=4, double-buffered) ----
// grid (L/MQ, B, SPLIT), 128 threads; warp w owns rows w*32..w*32+31 (2 m-groups).
#define KHO 0u
#define VHO 9216u
#define VLO 18432u
#define STAGEB 27648u

__device__ __forceinline__ void load_kv(uint32_t sbase, int b, int j0, int t) {
#pragma unroll
    for (int i = 0; i < 4; ++i) {
        int idx = t + i * 128;
        int r = idx >> 3, c = idx & 7;
        uint32_t so = (uint32_t)((r * STRD + c * 8) * 2);
        size_t kg = ((size_t)b * L + j0 + r) * 64 + c * 8;
        cpa16(sbase + KHO + so, g_Khi + kg);
        size_t vg = ((size_t)b * 64 + r) * L + j0 + c * 8;
        cpa16(sbase + VHO + so, g_Vthi + vg);
        cpa16(sbase + VLO + so, g_Vtlo + vg);
    }
}

__global__ __launch_bounds__(128, 2) void attn_kernel() {
    extern __shared__ char sm[];
    const uint32_t sb = smem_u32(sm);
    const int t = threadIdx.x, lane = t & 31, w = t >> 5;
    const int b = blockIdx.y, i0 = blockIdx.x * MQ, sp = blockIdx.z;
    const int jbase = sp * JSPAN;
    const int gid = lane >> 2, tig = lane & 3;
    const int lr = lane & 7, lg = lane >> 3;

    const uint32_t offA = (uint32_t)(((lr + ((lg & 1) << 3)) * STRD + ((lg >> 1) << 3)) * 2);
    const uint32_t offB = (uint32_t)(((lr + ((lg >> 1) << 3)) * STRD + ((lg & 1) << 3)) * 2);

    // ---- stage Q (128 rows) into stage-0, build persistent A fragments (2 m-groups)
    {
        const uint4* qh = (const uint4*)(g_Qhi + ((size_t)b * L + i0) * 64);
        for (int idx = t; idx < 1024; idx += 128) {
            int r = idx >> 3, c = idx & 7;
            uint32_t so = (uint32_t)((r * STRD + c * 8) * 2);
            *(uint4*)(sm + so) = qh[idx];
        }
    }
    __syncthreads();
    uint32_t qf[2][4][4];
#pragma unroll
    for (int mg = 0; mg < 2; ++mg) {
        uint32_t base = sb + (uint32_t)((w * 32 + mg * 16) * STRD * 2) + offA;
#pragma unroll
        for (int kb = 0; kb < 4; ++kb) ldsm4(qf[mg][kb], base + kb * 32);
    }
    __syncthreads();

    load_kv(sb, b, jbase, t);
    CPA_COMMIT();

    float O[2][8][4];
#pragma unroll
    for (int mg = 0; mg < 2; ++mg)
#pragma unroll
        for (int n = 0; n < 8; ++n)
#pragma unroll
            for (int q = 0; q < 4; ++q) O[mg][n][q] = 0.f;
    float dsum[2][2] = {{0.f, 0.f}, {0.f, 0.f}};

    for (int tile = 0; tile < NTILE; ++tile) {
        int cur = tile & 1;
        if (tile < NTILE - 1) {
            load_kv(sb + (uint32_t)(cur ^ 1) * STAGEB, b, jbase + (tile + 1) * 64, t);
            CPA_COMMIT();
            CPA_WAIT1();
        } else {
            CPA_WAIT0();
        }
        __syncthreads();

        const uint32_t bB = sb + (uint32_t)cur * STAGEB + offB;

        // ---- S = Q Khi^T for both m-groups (each B-frag ldsm feeds 4 mmas)
        float S[2][8][4];
#pragma unroll
        for (int mg = 0; mg < 2; ++mg)
#pragma unroll
            for (int n = 0; n < 8; ++n)
#pragma unroll
                for (int q = 0; q < 4; ++q) S[mg][n][q] = 0.f;

#pragma unroll
        for (int kb = 0; kb < 4; ++kb) {
#pragma unroll
            for (int np = 0; np < 4; ++np) {
                uint32_t bh[4];
                ldsm4(bh, bB + KHO + (uint32_t)(np * 16 * STRD * 2) + kb * 32);
                mma_bf16(S[0][np * 2],     qf[0][kb], bh[0], bh[1]);
                mma_bf16(S[0][np * 2 + 1], qf[0][kb], bh[2], bh[3]);
                mma_bf16(S[1][np * 2],     qf[1][kb], bh[0], bh[1]);
                mma_bf16(S[1][np * 2 + 1], qf[1][kb], bh[2], bh[3]);
            }
        }

        // ---- exp, row sums, hi/lo pack -> P fragments
        uint32_t phi[2][4][4], plo[2][4][4];
#pragma unroll
        for (int mg = 0; mg < 2; ++mg) {
            float rl = 0.f, rh = 0.f;
#pragma unroll
            for (int n = 0; n < 8; ++n) {
#pragma unroll
                for (int q = 0; q < 4; ++q) S[mg][n][q] = __expf(S[mg][n][q]);
                rl += S[mg][n][0] + S[mg][n][1];
                rh += S[mg][n][2] + S[mg][n][3];
            }
            dsum[mg][0] += rl; dsum[mg][1] += rh;
#pragma unroll
            for (int jb = 0; jb < 4; ++jb) {
#pragma unroll
                for (int rp = 0; rp < 4; ++rp) {
                    int n = jb * 2 + (rp >> 1);
                    float e0 = S[mg][n][(rp & 1) * 2 + 0];
                    float e1 = S[mg][n][(rp & 1) * 2 + 1];
                    uint32_t hh;
                    asm("cvt.rn.bf16x2.f32 %0, %1, %2;" : "=r"(hh) : "f"(e1), "f"(e0));
                    phi[mg][jb][rp] = hh;
                    float l0 = e0 - __uint_as_float(hh << 16);
                    float l1 = e1 - __uint_as_float(hh & 0xffff0000u);
                    uint32_t ll;
                    asm("cvt.rn.bf16x2.f32 %0, %1, %2;" : "=r"(ll) : "f"(l1), "f"(l0));
                    plo[mg][jb][rp] = ll;
                }
            }
        }

        // ---- O += Phi Vhi + Plo Vhi + Phi Vlo (both m-groups share B-frags)
#pragma unroll
        for (int jb = 0; jb < 4; ++jb) {
#pragma unroll
            for (int vp = 0; vp < 4; ++vp) {
                uint32_t bh[4], bl[4];
                ldsm4(bh, bB + VHO + (uint32_t)(vp * 16 * STRD * 2) + jb * 32);
                mma_bf16(O[0][vp * 2],     phi[0][jb], bh[0], bh[1]);
                mma_bf16(O[0][vp * 2 + 1], phi[0][jb], bh[2], bh[3]);
                mma_bf16(O[0][vp * 2],     plo[0][jb], bh[0], bh[1]);
                mma_bf16(O[0][vp * 2 + 1], plo[0][jb], bh[2], bh[3]);
                mma_bf16(O[1][vp * 2],     phi[1][jb], bh[0], bh[1]);
                mma_bf16(O[1][vp * 2 + 1], phi[1][jb], bh[2], bh[3]);
                mma_bf16(O[1][vp * 2],     plo[1][jb], bh[0], bh[1]);
                mma_bf16(O[1][vp * 2 + 1], plo[1][jb], bh[2], bh[3]);
                ldsm4(bl, bB + VLO + (uint32_t)(vp * 16 * STRD * 2) + jb * 32);
                mma_bf16(O[0][vp * 2],     phi[0][jb], bl[0], bl[1]);
                mma_bf16(O[0][vp * 2 + 1], phi[0][jb], bl[2], bl[3]);
                mma_bf16(O[1][vp * 2],     phi[1][jb], bl[0], bl[1]);
                mma_bf16(O[1][vp * 2 + 1], phi[1][jb], bl[2], bl[3]);
            }
        }
        __syncthreads();
    }

    // row-sum reduce across lanes; store partial denoms
#pragma unroll
    for (int mg = 0; mg < 2; ++mg) {
#pragma unroll
        for (int h = 0; h < 2; ++h) {
            float v = dsum[mg][h];
            v += __shfl_xor_sync(0xffffffffu, v, 1);
            v += __shfl_xor_sync(0xffffffffu, v, 2);
            if (tig == 0)
                g_pd[sp][(size_t)b * L + i0 + w * 32 + mg * 16 + gid + h * 8] = v;
        }
    }

    // ---- write partial O (un-normalized) in [v][i] layout via smem transpose
    __syncthreads();
    float* Os = (float*)sm;   // [64][132] floats = 33792B
#pragma unroll
    for (int mg = 0; mg < 2; ++mg) {
        int ir = w * 32 + mg * 16 + gid;
#pragma unroll
        for (int n = 0; n < 8; ++n) {
            int v0 = n * 8 + tig * 2;
            Os[v0 * 132 + ir]            = O[mg][n][0];
            Os[(v0 + 1) * 132 + ir]      = O[mg][n][1];
            Os[v0 * 132 + ir + 8]        = O[mg][n][2];
            Os[(v0 + 1) * 132 + ir + 8]  = O[mg][n][3];
        }
    }
    __syncthreads();
    {
        int v = t >> 1, hc = (t & 1) * 64;
        float* dst = g_pO[sp] + ((size_t)b * 64 + v) * L + i0 + hc;
        const float* srcp = Os + v * 132 + hc;
#pragma unroll
        for (int c = 0; c < 16; ++c)
            *(float4*)(dst + c * 4) = *(const float4*)(srcp + c * 4);
    }
}

// ---------------- combine: out = sum(O_s) / sum(d_s) ----------------
__global__ __launch_bounds__(256) void combine_kernel(float* __restrict__ out) {
    int e0 = (blockIdx.x * 256 + threadIdx.x) * 8;   // index into [b][v][i]
    int b = e0 >> 18;
    int i = e0 & (L - 1);
    float num[8], den[8];
#pragma unroll
    for (int k = 0; k < 8; ++k) { num[k] = 0.f; den[k] = 0.f; }
#pragma unroll
    for (int s = 0; s < SPLIT; ++s) {
        float4 pa = *(const float4*)&g_pO[s][e0];
        float4 pb = *(const float4*)&g_pO[s][e0 + 4];
        float4 da = *(const float4*)&g_pd[s][(size_t)b * L + i];
        float4 db = *(const float4*)&g_pd[s][(size_t)b * L + i + 4];
        num[0] += pa.x; num[1] += pa.y; num[2] += pa.z; num[3] += pa.w;
        num[4] += pb.x; num[5] += pb.y; num[6] += pb.z; num[7] += pb.w;
        den[0] += da.x; den[1] += da.y; den[2] += da.z; den[3] += da.w;
        den[4] += db.x; den[5] += db.y; den[6] += db.z; den[7] += db.w;
    }
    float4 oa, ob;
    oa.x = num[0] / den[0]; oa.y = num[1] / den[1];
    oa.z = num[2] / den[2]; oa.w = num[3] / den[3];
    ob.x = num[4] / den[4]; ob.y = num[5] / den[5];
    ob.z = num[6] / den[6]; ob.w = num[7] / den[7];
    *(float4*)&out[e0]     = oa;
    *(float4*)&out[e0 + 4] = ob;
}

// ---------------- launch ----------------
extern "C" void kernel_launch(void* const* d_in, const int* in_sizes, int n_in,
                              void* d_out, int out_size) {
    const float* x     = (const float*)d_in[0];
    const float* x_enc = (const float*)d_in[1];
    const float* Wq    = (const float*)d_in[2];
    const float* bq    = (const float*)d_in[3];
    const float* Wk    = (const float*)d_in[4];
    const float* bk    = (const float*)d_in[5];
    const float* Wv    = (const float*)d_in[6];
    const float* bv    = (const float*)d_in[7];
    float* out = (float*)d_out;

    prep_w_kernel<<<(64 * CENC_P + 255) / 256, 256>>>(Wq, CENC, CENC_P, 0);
    prep_w_kernel<<<(64 * CENC_P + 255) / 256, 256>>>(Wk, CENC, CENC_P, 1);
    prep_w_kernel<<<(64 * CIN_P  + 255) / 256, 256>>>(Wv, CIN,  CIN_P,  2);

    proj_kernel<<<dim3(L / 64, B, 2), 128, 18432>>>(x, x_enc, bq, bk, bv);

    static bool attr_set = false;
    if (!attr_set) {
        cudaFuncSetAttribute(attn_kernel, cudaFuncAttributeMaxDynamicSharedMemorySize,
                             2 * STAGEB);
        attr_set = true;
    }
    attn_kernel<<<dim3(L / MQ, B, SPLIT), 128, 2 * STAGEB>>>();

    combine_kernel<<<(B * 64 * L) / (256 * 8), 256>>>(out);
}

// round 9
// speedup vs baseline: 7.9924x; 1.0429x over previous
#include <cuda_runtime.h>
#include <cuda_bf16.h>
#include <math.h>
#include <stdint.h>

#define B    2
#define CIN  320
#define CENC 326
#define L    4096

#define CENC_P 336   // padded to multiple of 16
#define CIN_P  320

#define STRD 72      // bf16 row stride, K/Q attention tiles (144B)
#define VSTR 136     // bf16 row stride, V attention tiles (272B; 128-j rows)
#define WST  24      // bf16 row stride in proj smem tiles (48B rows)

#define SPLIT 4
#define JSPAN (L / SPLIT)    // 1024
#define NJ    128
#define NTILE (JSPAN / NJ)   // 8
#define MQ    128            // queries per CTA (32 rows per warp, 2 m-groups)

// ---------------- scratch (device globals) ----------------
__device__ __nv_bfloat16 g_Qhi[B * L * 64];
__device__ __nv_bfloat16 g_Khi[B * L * 64];
__device__ __nv_bfloat16 g_Vthi[B * 64 * L], g_Vtlo[B * 64 * L];   // [b][v][l]
__device__ __nv_bfloat16 g_Whq[64 * CENC_P], g_Wlq[64 * CENC_P];   // [d][c] hi/lo
__device__ __nv_bfloat16 g_Whk[64 * CENC_P], g_Wlk[64 * CENC_P];
__device__ __nv_bfloat16 g_Whv[64 * CIN_P],  g_Wlv[64 * CIN_P];
__device__ float g_pO[SPLIT][B * 64 * L];    // partial O, [sp][b][v][i]
__device__ float g_pd[SPLIT][B * L];         // partial denominators

// ---------------- helpers ----------------
__device__ __forceinline__ uint32_t smem_u32(const void* p) {
    uint32_t a;
    asm("{ .reg .u64 t; cvta.to.shared.u64 t, %1; cvt.u32.u64 %0, t; }" : "=r"(a) : "l"(p));
    return a;
}
__device__ __forceinline__ void ldsm4(uint32_t r[4], uint32_t addr) {
    asm volatile("ldmatrix.sync.aligned.m8n8.x4.shared.b16 {%0,%1,%2,%3}, [%4];"
        : "=r"(r[0]), "=r"(r[1]), "=r"(r[2]), "=r"(r[3]) : "r"(addr));
}
__device__ __forceinline__ void mma_bf16(float c[4], const uint32_t a[4],
                                         uint32_t b0, uint32_t b1) {
    asm volatile("mma.sync.aligned.m16n8k16.row.col.f32.bf16.bf16.f32 "
        "{%0,%1,%2,%3}, {%4,%5,%6,%7}, {%8,%9}, {%0,%1,%2,%3};"
        : "+f"(c[0]), "+f"(c[1]), "+f"(c[2]), "+f"(c[3])
        : "r"(a[0]), "r"(a[1]), "r"(a[2]), "r"(a[3]), "r"(b0), "r"(b1));
}
__device__ __forceinline__ void cpa16(uint32_t dst, const void* src) {
    asm volatile("cp.async.cg.shared.global [%0], [%1], 16;" :: "r"(dst), "l"(src));
}
#define CPA_COMMIT() asm volatile("cp.async.commit_group;" ::: "memory")
#define CPA_WAIT1()  asm volatile("cp.async.wait_group 1;" ::: "memory")
#define CPA_WAIT0()  asm volatile("cp.async.wait_group 0;" ::: "memory")

// ---------------- weight prep (single launch): W[d][c] fp32 -> bf16 hi/lo ----------
__global__ void prep_w_kernel(const float* __restrict__ Wq, const float* __restrict__ Wk,
                              const float* __restrict__ Wv) {
    int which = blockIdx.y;
    const float* W = (which == 0) ? Wq : (which == 1) ? Wk : Wv;
    __nv_bfloat16* Wh = (which == 0) ? g_Whq : (which == 1) ? g_Whk : g_Whv;
    __nv_bfloat16* Wl = (which == 0) ? g_Wlq : (which == 1) ? g_Wlk : g_Wlv;
    int Cdim = (which == 2) ? CIN : CENC;
    int Cpad = (which == 2) ? CIN_P : CENC_P;
    int idx = blockIdx.x * blockDim.x + threadIdx.x;
    if (idx < 64 * Cpad) {
        int d = idx / Cpad, c = idx - d * Cpad;
        float v = (c < Cdim) ? W[d * Cdim + c] : 0.f;
        __nv_bfloat16 h = __float2bfloat16(v);
        Wh[idx] = h;
        Wl[idx] = __float2bfloat16(v - __bfloat162float(h));
    }
}

// ---------------- tensor-core projections (unfused; round-7 design) ----------------
// grid (L/64, B, 3), 128 threads. out[64 d][64 l] = W[64][C] @ X[C][64-l-tile]
__global__ __launch_bounds__(128) void proj_kernel(const float* __restrict__ x,
                                                   const float* __restrict__ x_enc,
                                                   const float* __restrict__ bq,
                                                   const float* __restrict__ bk,
                                                   const float* __restrict__ bv) {
    int z = blockIdx.z, b = blockIdx.y, l0 = blockIdx.x * 64;
    const float* src  = (z == 2) ? x : x_enc;
    const __nv_bfloat16* Wh = (z == 0) ? g_Whq : (z == 1) ? g_Whk : g_Whv;
    const __nv_bfloat16* Wl = (z == 0) ? g_Wlq : (z == 1) ? g_Wlk : g_Wlv;
    const float* bias = (z == 0) ? bq : (z == 1) ? bk : bv;
    int Cdim = (z == 2) ? CIN : CENC;
    int Cpad = (z == 2) ? CIN_P : CENC_P;

    extern __shared__ char psm[];
    __nv_bfloat16* Xh  = (__nv_bfloat16*)(psm);
    __nv_bfloat16* Xl  = (__nv_bfloat16*)(psm + 3072);
    __nv_bfloat16* Whs = (__nv_bfloat16*)(psm + 6144);
    __nv_bfloat16* Wls = (__nv_bfloat16*)(psm + 9216);
    __shared__ float nrmA[64];
    uint32_t sb = smem_u32(psm);

    int t = threadIdx.x, lane = t & 31, w = t >> 5;
    int gid = lane >> 2, tig = lane & 3, lr = lane & 7, lg = lane >> 3;

    float S[8][4];
#pragma unroll
    for (int n = 0; n < 8; ++n)
#pragma unroll
        for (int q = 0; q < 4; ++q) S[n][q] = 0.f;

    const float* srcb = src + (size_t)b * Cdim * L + l0;
    const uint32_t offB = (uint32_t)(((lr + (lg >> 1) * 8) * WST + (lg & 1) * 8) * 2);
    const uint32_t bX = sb + offB;

    int nCh = Cpad / 16;

    float xv[8];
#pragma unroll
    for (int i = 0; i < 8; ++i) {
        int idx = t + i * 128;
        int c = idx >> 6, l = idx & 63;
        xv[i] = (c < Cdim) ? __ldg(srcb + (size_t)c * L + l) : 0.f;
    }

    for (int ch = 0; ch < nCh; ++ch) {
        int c0 = ch * 16;
        __syncthreads();
#pragma unroll
        for (int i = 0; i < 8; ++i) {
            int idx = t + i * 128;
            int c = idx >> 6, l = idx & 63;
            __nv_bfloat16 h = __float2bfloat16(xv[i]);
            Xh[l * WST + c] = h;
            Xl[l * WST + c] = __float2bfloat16(xv[i] - __bfloat162float(h));
        }
#pragma unroll
        for (int i = 0; i < 4; ++i) {
            int idx = t + i * 128;
            int d = idx >> 3, cp = idx & 7;
            *(uint32_t*)&Whs[d * WST + cp * 2] = *(const uint32_t*)&Wh[d * Cpad + c0 + cp * 2];
            *(uint32_t*)&Wls[d * WST + cp * 2] = *(const uint32_t*)&Wl[d * Cpad + c0 + cp * 2];
        }
        __syncthreads();

        if (ch + 1 < nCh) {
            int c1 = (ch + 1) * 16;
#pragma unroll
            for (int i = 0; i < 8; ++i) {
                int idx = t + i * 128;
                int c = c1 + (idx >> 6), l = idx & 63;
                xv[i] = (c < Cdim) ? __ldg(srcb + (size_t)c * L + l) : 0.f;
            }
        }

        uint32_t ah[4], al[4];
        {
            int r0 = (w * 16 + gid) * WST, r8 = (w * 16 + gid + 8) * WST;
            ah[0] = *(const uint32_t*)&Whs[r0 + tig * 2];
            ah[1] = *(const uint32_t*)&Whs[r8 + tig * 2];
            ah[2] = *(const uint32_t*)&Whs[r0 + tig * 2 + 8];
            ah[3] = *(const uint32_t*)&Whs[r8 + tig * 2 + 8];
            al[0] = *(const uint32_t*)&Wls[r0 + tig * 2];
            al[1] = *(const uint32_t*)&Wls[r8 + tig * 2];
            al[2] = *(const uint32_t*)&Wls[r0 + tig * 2 + 8];
            al[3] = *(const uint32_t*)&Wls[r8 + tig * 2 + 8];
        }

#pragma unroll
        for (int np = 0; np < 4; ++np) {
            uint32_t bh[4], bl[4];
            ldsm4(bh, bX + (uint32_t)(np * 16 * WST * 2));
            mma_bf16(S[np * 2],     ah, bh[0], bh[1]);
            mma_bf16(S[np * 2 + 1], ah, bh[2], bh[3]);
            mma_bf16(S[np * 2],     al, bh[0], bh[1]);
            mma_bf16(S[np * 2 + 1], al, bh[2], bh[3]);
            ldsm4(bl, bX + 3072u + (uint32_t)(np * 16 * WST * 2));
            mma_bf16(S[np * 2],     ah, bl[0], bl[1]);
            mma_bf16(S[np * 2 + 1], ah, bl[2], bl[3]);
        }
    }

    float b0v = __ldg(bias + w * 16 + gid);
    float b8v = __ldg(bias + w * 16 + gid + 8);

    float* Osm = (float*)psm;   // [64][68] floats = 17408B
    __syncthreads();

    if (z < 2) {
#pragma unroll
        for (int n = 0; n < 8; ++n) {
            int lc = n * 8 + tig * 2, d0 = w * 16 + gid;
            Osm[lc * 68 + d0]           = S[n][0] + b0v;
            Osm[(lc + 1) * 68 + d0]     = S[n][1] + b0v;
            Osm[lc * 68 + d0 + 8]       = S[n][2] + b8v;
            Osm[(lc + 1) * 68 + d0 + 8] = S[n][3] + b8v;
        }
        __syncthreads();
        if (t < 64) {
            float ss = 0.f;
#pragma unroll
            for (int d = 0; d < 64; ++d) { float v = Osm[t * 68 + d]; ss += v * v; }
            nrmA[t] = 1.f / fmaxf(sqrtf(ss), 1e-6f);
        }
        __syncthreads();
        __nv_bfloat16* dh = (z == 0) ? g_Qhi : g_Khi;
        int l = t & 63, dg = t >> 6;
        float sc = nrmA[l];
        size_t obase = ((size_t)b * L + l0 + l) * 64 + dg * 32;
#pragma unroll
        for (int i = 0; i < 8; ++i) {
            __nv_bfloat16 th[4];
#pragma unroll
            for (int k = 0; k < 4; ++k)
                th[k] = __float2bfloat16(Osm[l * 68 + dg * 32 + i * 4 + k] * sc);
            *(uint2*)&dh[obase + i * 4] = *(uint2*)th;
        }
    } else {
#pragma unroll
        for (int n = 0; n < 8; ++n) {
            int lc = n * 8 + tig * 2, d0 = w * 16 + gid;
            Osm[d0 * 68 + lc]           = S[n][0] + b0v;
            Osm[d0 * 68 + lc + 1]       = S[n][1] + b0v;
            Osm[(d0 + 8) * 68 + lc]     = S[n][2] + b8v;
            Osm[(d0 + 8) * 68 + lc + 1] = S[n][3] + b8v;
        }
        __syncthreads();
        int v = t >> 1, half = t & 1;
        size_t obase = ((size_t)b * 64 + v) * L + l0 + half * 32;
#pragma unroll
        for (int i = 0; i < 8; ++i) {
            __nv_bfloat16 th[4], tl[4];
#pragma unroll
            for (int k = 0; k < 4; ++k) {
                float vv = Osm[v * 68 + half * 32 + i * 4 + k];
                th[k] = __float2bfloat16(vv);
                tl[k] = __float2bfloat16(vv - __bfloat162float(th[k]));
            }
            *(uint2*)&g_Vthi[obase + i * 4] = *(uint2*)th;
            *(uint2*)&g_Vtlo[obase + i * 4] = *(uint2*)tl;
        }
    }
}

// ---------------- mma.sync flash attention (MQ=128, NJ=128, split-j=4) ----------
#define KHO  0u
#define VHO  18432u
#define VLO  35840u
#define STAGEB 53248u

__device__ __forceinline__ void load_kv(uint32_t sbase, int b, int j0, int t) {
    // K: 128 rows x 144B
#pragma unroll
    for (int i = 0; i < 8; ++i) {
        int idx = t + i * 128;
        int r = idx >> 3, c = idx & 7;
        cpa16(sbase + KHO + (uint32_t)(r * 144 + c * 16),
              g_Khi + ((size_t)b * L + j0 + r) * 64 + c * 8);
    }
    // V hi/lo: 64 rows x 256B data (272B stride)
#pragma unroll
    for (int i = 0; i < 8; ++i) {
        int idx = t + i * 128;
        int v = idx >> 4, c16 = idx & 15;
        uint32_t so = (uint32_t)(v * 272 + c16 * 16);
        size_t vg = ((size_t)b * 64 + v) * L + j0 + c16 * 8;
        cpa16(sbase + VHO + so, g_Vthi + vg);
        cpa16(sbase + VLO + so, g_Vtlo + vg);
    }
}

__global__ __launch_bounds__(128, 2) void attn_kernel() {
    extern __shared__ char sm[];
    const uint32_t sb = smem_u32(sm);
    const int t = threadIdx.x, lane = t & 31, w = t >> 5;
    const int b = blockIdx.y, i0 = blockIdx.x * MQ, sp = blockIdx.z;
    const int jbase = sp * JSPAN;
    const int gid = lane >> 2, tig = lane & 3;
    const int lr = lane & 7, lg = lane >> 3;

    const uint32_t offA  = (uint32_t)(((lr + ((lg & 1) << 3)) * STRD + ((lg >> 1) << 3)) * 2);
    const uint32_t offBK = (uint32_t)(((lr + ((lg >> 1) << 3)) * STRD + ((lg & 1) << 3)) * 2);
    const uint32_t offBV = (uint32_t)(((lr + ((lg >> 1) << 3)) * VSTR + ((lg & 1) << 3)) * 2);

    // ---- stage Q (128 rows) into stage-0 K area, build persistent A fragments
    {
        const uint4* qh = (const uint4*)(g_Qhi + ((size_t)b * L + i0) * 64);
        for (int idx = t; idx < 1024; idx += 128) {
            int r = idx >> 3, c = idx & 7;
            *(uint4*)(sm + (uint32_t)(r * 144 + c * 16)) = qh[idx];
        }
    }
    __syncthreads();
    uint32_t qf[2][4][4];
#pragma unroll
    for (int mg = 0; mg < 2; ++mg) {
        uint32_t base = sb + (uint32_t)((w * 32 + mg * 16) * STRD * 2) + offA;
#pragma unroll
        for (int kb = 0; kb < 4; ++kb) ldsm4(qf[mg][kb], base + kb * 32);
    }
    __syncthreads();

    load_kv(sb, b, jbase, t);
    CPA_COMMIT();

    float O[2][8][4];
#pragma unroll
    for (int mg = 0; mg < 2; ++mg)
#pragma unroll
        for (int n = 0; n < 8; ++n)
#pragma unroll
            for (int q = 0; q < 4; ++q) O[mg][n][q] = 0.f;
    float dsum[2][2] = {{0.f, 0.f}, {0.f, 0.f}};

#pragma unroll 1
    for (int tile = 0; tile < NTILE; ++tile) {
        int cur = tile & 1;
        if (tile < NTILE - 1) {
            load_kv(sb + (uint32_t)(cur ^ 1) * STAGEB, b, jbase + (tile + 1) * NJ, t);
            CPA_COMMIT();
            CPA_WAIT1();
        } else {
            CPA_WAIT0();
        }
        __syncthreads();

        const uint32_t stg = sb + (uint32_t)cur * STAGEB;

#pragma unroll
        for (int jh = 0; jh < 2; ++jh) {
            const uint32_t bBK = stg + KHO + offBK + (uint32_t)(jh * 64 * 144);
            const uint32_t bBV = stg + VHO + offBV + (uint32_t)(jh * 128);

            // ---- S = Q Khi^T for both m-groups
            float S[2][8][4];
#pragma unroll
            for (int mg = 0; mg < 2; ++mg)
#pragma unroll
                for (int n = 0; n < 8; ++n)
#pragma unroll
                    for (int q = 0; q < 4; ++q) S[mg][n][q] = 0.f;

#pragma unroll
            for (int kb = 0; kb < 4; ++kb) {
#pragma unroll
                for (int np = 0; np < 4; ++np) {
                    uint32_t bh[4];
                    ldsm4(bh, bBK + (uint32_t)(np * 16 * STRD * 2) + kb * 32);
                    mma_bf16(S[0][np * 2],     qf[0][kb], bh[0], bh[1]);
                    mma_bf16(S[0][np * 2 + 1], qf[0][kb], bh[2], bh[3]);
                    mma_bf16(S[1][np * 2],     qf[1][kb], bh[0], bh[1]);
                    mma_bf16(S[1][np * 2 + 1], qf[1][kb], bh[2], bh[3]);
                }
            }

            // ---- exp, row sums, hi/lo pack -> P fragments
            uint32_t phi[2][4][4], plo[2][4][4];
#pragma unroll
            for (int mg = 0; mg < 2; ++mg) {
                float rl = 0.f, rh = 0.f;
#pragma unroll
                for (int n = 0; n < 8; ++n) {
#pragma unroll
                    for (int q = 0; q < 4; ++q) S[mg][n][q] = __expf(S[mg][n][q]);
                    rl += S[mg][n][0] + S[mg][n][1];
                    rh += S[mg][n][2] + S[mg][n][3];
                }
                dsum[mg][0] += rl; dsum[mg][1] += rh;
#pragma unroll
                for (int jb = 0; jb < 4; ++jb) {
#pragma unroll
                    for (int rp = 0; rp < 4; ++rp) {
                        int n = jb * 2 + (rp >> 1);
                        float e0 = S[mg][n][(rp & 1) * 2 + 0];
                        float e1 = S[mg][n][(rp & 1) * 2 + 1];
                        uint32_t hh;
                        asm("cvt.rn.bf16x2.f32 %0, %1, %2;" : "=r"(hh) : "f"(e1), "f"(e0));
                        phi[mg][jb][rp] = hh;
                        float l0 = e0 - __uint_as_float(hh << 16);
                        float l1 = e1 - __uint_as_float(hh & 0xffff0000u);
                        uint32_t ll;
                        asm("cvt.rn.bf16x2.f32 %0, %1, %2;" : "=r"(ll) : "f"(l1), "f"(l0));
                        plo[mg][jb][rp] = ll;
                    }
                }
            }

            // ---- O += Phi Vhi + Plo Vhi + Phi Vlo
#pragma unroll
            for (int jb = 0; jb < 4; ++jb) {
#pragma unroll
                for (int vp = 0; vp < 4; ++vp) {
                    uint32_t bh[4], bl[4];
                    ldsm4(bh, bBV + (uint32_t)(vp * 16 * VSTR * 2) + jb * 32);
                    mma_bf16(O[0][vp * 2],     phi[0][jb], bh[0], bh[1]);
                    mma_bf16(O[0][vp * 2 + 1], phi[0][jb], bh[2], bh[3]);
                    mma_bf16(O[0][vp * 2],     plo[0][jb], bh[0], bh[1]);
                    mma_bf16(O[0][vp * 2 + 1], plo[0][jb], bh[2], bh[3]);
                    mma_bf16(O[1][vp * 2],     phi[1][jb], bh[0], bh[1]);
                    mma_bf16(O[1][vp * 2 + 1], phi[1][jb], bh[2], bh[3]);
                    mma_bf16(O[1][vp * 2],     plo[1][jb], bh[0], bh[1]);
                    mma_bf16(O[1][vp * 2 + 1], plo[1][jb], bh[2], bh[3]);
                    ldsm4(bl, bBV + (uint32_t)((VLO - VHO) + vp * 16 * VSTR * 2) + jb * 32);
                    mma_bf16(O[0][vp * 2],     phi[0][jb], bl[0], bl[1]);
                    mma_bf16(O[0][vp * 2 + 1], phi[0][jb], bl[2], bl[3]);
                    mma_bf16(O[1][vp * 2],     phi[1][jb], bl[0], bl[1]);
                    mma_bf16(O[1][vp * 2 + 1], phi[1][jb], bl[2], bl[3]);
                }
            }
        }
        __syncthreads();
    }

    // row-sum reduce across lanes; store partial denoms
#pragma unroll
    for (int mg = 0; mg < 2; ++mg) {
#pragma unroll
        for (int h = 0; h < 2; ++h) {
            float v = dsum[mg][h];
            v += __shfl_xor_sync(0xffffffffu, v, 1);
            v += __shfl_xor_sync(0xffffffffu, v, 2);
            if (tig == 0)
                g_pd[sp][(size_t)b * L + i0 + w * 32 + mg * 16 + gid + h * 8] = v;
        }
    }

    // ---- write partial O (un-normalized) in [v][i] layout via smem transpose
    __syncthreads();
    float* Os = (float*)sm;   // [64][132] floats = 33792B
#pragma unroll
    for (int mg = 0; mg < 2; ++mg) {
        int ir = w * 32 + mg * 16 + gid;
#pragma unroll
        for (int n = 0; n < 8; ++n) {
            int v0 = n * 8 + tig * 2;
            Os[v0 * 132 + ir]            = O[mg][n][0];
            Os[(v0 + 1) * 132 + ir]      = O[mg][n][1];
            Os[v0 * 132 + ir + 8]        = O[mg][n][2];
            Os[(v0 + 1) * 132 + ir + 8]  = O[mg][n][3];
        }
    }
    __syncthreads();
    {
        int v = t >> 1, hc = (t & 1) * 64;
        float* dst = g_pO[sp] + ((size_t)b * 64 + v) * L + i0 + hc;
        const float* srcp = Os + v * 132 + hc;
#pragma unroll
        for (int c = 0; c < 16; ++c)
            *(float4*)(dst + c * 4) = *(const float4*)(srcp + c * 4);
    }
}

// ---------------- combine: out = sum(O_s) / sum(d_s) ----------------
__global__ __launch_bounds__(256) void combine_kernel(float* __restrict__ out) {
    int e0 = (blockIdx.x * 256 + threadIdx.x) * 8;
    int b = e0 >> 18;
    int i = e0 & (L - 1);
    float num[8], den[8];
#pragma unroll
    for (int k = 0; k < 8; ++k) { num[k] = 0.f; den[k] = 0.f; }
#pragma unroll
    for (int s = 0; s < SPLIT; ++s) {
        float4 pa = *(const float4*)&g_pO[s][e0];
        float4 pb = *(const float4*)&g_pO[s][e0 + 4];
        float4 da = *(const float4*)&g_pd[s][(size_t)b * L + i];
        float4 db = *(const float4*)&g_pd[s][(size_t)b * L + i + 4];
        num[0] += pa.x; num[1] += pa.y; num[2] += pa.z; num[3] += pa.w;
        num[4] += pb.x; num[5] += pb.y; num[6] += pb.z; num[7] += pb.w;
        den[0] += da.x; den[1] += da.y; den[2] += da.z; den[3] += da.w;
        den[4] += db.x; den[5] += db.y; den[6] += db.z; den[7] += db.w;
    }
    float4 oa, ob;
    oa.x = num[0] / den[0]; oa.y = num[1] / den[1];
    oa.z = num[2] / den[2]; oa.w = num[3] / den[3];
    ob.x = num[4] / den[4]; ob.y = num[5] / den[5];
    ob.z = num[6] / den[6]; ob.w = num[7] / den[7];
    *(float4*)&out[e0]     = oa;
    *(float4*)&out[e0 + 4] = ob;
}

// ---------------- launch ----------------
extern "C" void kernel_launch(void* const* d_in, const int* in_sizes, int n_in,
                              void* d_out, int out_size) {
    const float* x     = (const float*)d_in[0];
    const float* x_enc = (const float*)d_in[1];
    const float* Wq    = (const float*)d_in[2];
    const float* bq    = (const float*)d_in[3];
    const float* Wk    = (const float*)d_in[4];
    const float* bk    = (const float*)d_in[5];
    const float* Wv    = (const float*)d_in[6];
    const float* bv    = (const float*)d_in[7];
    float* out = (float*)d_out;

    prep_w_kernel<<<dim3((64 * CENC_P + 255) / 256, 3), 256>>>(Wq, Wk, Wv);

    proj_kernel<<<dim3(L / 64, B, 3), 128, 17408>>>(x, x_enc, bq, bk, bv);

    static bool attr_set = false;
    if (!attr_set) {
        cudaFuncSetAttribute(attn_kernel, cudaFuncAttributeMaxDynamicSharedMemorySize,
                             2 * STAGEB);
        attr_set = true;
    }
    attn_kernel<<<dim3(L / MQ, B, SPLIT), 128, 2 * STAGEB>>>();

    combine_kernel<<<(B * 64 * L) / (256 * 8), 256>>>(out);
}